// round 13
// baseline (speedup 1.0000x reference)
#include <cuda_runtime.h>
#include <cuda_fp16.h>
#include <cstdint>

// Problem constants
#define Bb 2
#define Ss 2048
#define Ee 1024
#define Hh 16
#define Dh 64
#define Mm (Bb*Ss)    // 4096
#define BHh (Bb*Hh)   // 32

#define LOG2E 1.4426950408889634f

// Scratch (device globals: allocation-guard-safe)
__device__ float  g_Xq[(size_t)Mm * Ee];         // tf32-rounded query
__device__ float  g_Xk[(size_t)Mm * Ee];         // tf32-rounded key
__device__ float  g_Xv[(size_t)Mm * Ee];         // tf32-rounded value
__device__ float  g_W[(size_t)4 * Ee * Ee];      // tf32-rounded Wq|Wk|Wv|Wo
__device__ __half g_Q[(size_t)BHh * Ss * Dh];    // [b,h,s,d] fp16
__device__ __half g_K[(size_t)BHh * Ss * Dh];    // [b,h,s,d] fp16
__device__ __half g_Vt[(size_t)BHh * Dh * Ss];   // [b,h,d,s] fp16
__device__ __half g_P[(size_t)BHh * Ss * Ss];    // 256 MB mixed logits * log2e, fp16
__device__ float  g_attn[(size_t)Mm * Ee];       // attention out (tf32 bits)

__device__ __forceinline__ uint32_t f2tf32(float f) {
    uint32_t u;
    asm("cvt.rna.tf32.f32 %0, %1;" : "=r"(u) : "f"(f));
    return u;
}

__device__ __forceinline__ uint32_t pack2h(float a, float b) {
    __half2 h = __floats2half2_rn(a, b);
    return *(uint32_t*)&h;
}

__device__ __forceinline__ float ex2f(float x) {
    float r;
    asm("ex2.approx.f32 %0, %1;" : "=f"(r) : "f"(x));
    return r;
}

// ---- packed f32x2 helpers (Blackwell f32x2 pipe) ----
__device__ __forceinline__ unsigned long long pk2(float x, float y) {
    unsigned long long r;
    asm("mov.b64 %0, {%1, %2};" : "=l"(r) : "f"(x), "f"(y));
    return r;
}
__device__ __forceinline__ void upk2(float& x, float& y, unsigned long long r) {
    asm("mov.b64 {%0, %1}, %2;" : "=f"(x), "=f"(y) : "l"(r));
}
__device__ __forceinline__ unsigned long long fma2(
    unsigned long long a, unsigned long long b, unsigned long long c) {
    unsigned long long d;
    asm("fma.rn.f32x2 %0, %1, %2, %3;" : "=l"(d) : "l"(a), "l"(b), "l"(c));
    return d;
}

__device__ __forceinline__ void mma_tf32(float& c0, float& c1, float& c2, float& c3,
                                         uint32_t a0, uint32_t a1, uint32_t a2, uint32_t a3,
                                         uint32_t b0, uint32_t b1) {
    asm volatile(
        "mma.sync.aligned.m16n8k8.row.col.f32.tf32.tf32.f32 "
        "{%0,%1,%2,%3}, {%4,%5,%6,%7}, {%8,%9}, {%0,%1,%2,%3};\n"
        : "+f"(c0), "+f"(c1), "+f"(c2), "+f"(c3)
        : "r"(a0), "r"(a1), "r"(a2), "r"(a3), "r"(b0), "r"(b1));
}

__device__ __forceinline__ void mma_f16(float& c0, float& c1, float& c2, float& c3,
                                        uint32_t a0, uint32_t a1, uint32_t a2, uint32_t a3,
                                        uint32_t b0, uint32_t b1) {
    asm volatile(
        "mma.sync.aligned.m16n8k16.row.col.f32.f16.f16.f32 "
        "{%0,%1,%2,%3}, {%4,%5,%6,%7}, {%8,%9}, {%0,%1,%2,%3};\n"
        : "+f"(c0), "+f"(c1), "+f"(c2), "+f"(c3)
        : "r"(a0), "r"(a1), "r"(a2), "r"(a3), "r"(b0), "r"(b1));
}

__device__ __forceinline__ void cp16(uint32_t dst, const void* src) {
    asm volatile("cp.async.cg.shared.global [%0], [%1], 16;\n" :: "r"(dst), "l"(src));
}
#define CP_COMMIT() asm volatile("cp.async.commit_group;\n" ::: "memory")
#define CP_WAIT(n)  asm volatile("cp.async.wait_group %0;\n" :: "n"(n) : "memory")

__device__ __forceinline__ uint32_t smem_u32(const void* p) {
    uint32_t a;
    asm("{ .reg .u64 t; cvta.to.shared.u64 t, %1; cvt.u32.u64 %0, t; }" : "=r"(a) : "l"(p));
    return a;
}

// ---------------------------------------------------------------------------
// Round inputs + weights to tf32 (rna). grid (4096, 7), 256 thr, 4 floats/thr.
// ---------------------------------------------------------------------------
__global__ void __launch_bounds__(256) cvt_round_kernel(
    const float* __restrict__ q, const float* __restrict__ k,
    const float* __restrict__ v,
    const float* __restrict__ wq, const float* __restrict__ wk,
    const float* __restrict__ wv, const float* __restrict__ wo)
{
    const int t = blockIdx.y;
    const float* src; float* dst; int n;
    switch (t) {
        case 0: src = q;  dst = g_Xq;              n = Mm * Ee; break;
        case 1: src = k;  dst = g_Xk;              n = Mm * Ee; break;
        case 2: src = v;  dst = g_Xv;              n = Mm * Ee; break;
        case 3: src = wq; dst = g_W;               n = Ee * Ee; break;
        case 4: src = wk; dst = g_W + 1048576;     n = Ee * Ee; break;
        case 5: src = wv; dst = g_W + 2097152;     n = Ee * Ee; break;
        default:src = wo; dst = g_W + 3145728;     n = Ee * Ee; break;
    }
    const int idx = (blockIdx.x * 256 + threadIdx.x) * 4;
    if (idx < n) {
        float4 f = *(const float4*)(src + idx);
        uint4 o = { f2tf32(f.x), f2tf32(f.y), f2tf32(f.z), f2tf32(f.w) };
        *(uint4*)(dst + idx) = o;
    }
}

// ---------------------------------------------------------------------------
// cp.async GEMM mainloop (proven R10): C[128x128] = A @ B^T, tf32 bits, K=1024.
// ---------------------------------------------------------------------------
__device__ __forceinline__ void gemm_body_ca(
    const float* __restrict__ Ag, const float* __restrict__ Bg,
    char* sm, float acc[4][4][4])
{
    const int tid  = threadIdx.x;
    const int lane = tid & 31;
    const int wid  = tid >> 5;
    const int wm   = wid >> 2;
    const int wn   = wid & 3;

    const uint32_t sbase = smem_u32(sm);

    int gA[4]; uint32_t sOff[4];
#pragma unroll
    for (int l = 0; l < 4; l++) {
        const int idx = tid + 256 * l;
        const int row = idx >> 3, q = idx & 7;
        gA[l]   = row * Ee + q * 4;
        sOff[l] = (uint32_t)(row * 128 + ((q ^ ((row & 3) << 1)) << 4));
    }

#pragma unroll
    for (int i = 0; i < 4; i++)
#pragma unroll
        for (int j = 0; j < 4; j++)
#pragma unroll
            for (int r2 = 0; r2 < 4; r2++) acc[i][j][r2] = 0.f;

#define G_ISSUE(kt, st) do { \
        const uint32_t base_ = sbase + (uint32_t)(st) * 32768u; \
        const int ko_ = (kt) * 32; \
        _Pragma("unroll") \
        for (int l = 0; l < 4; l++) { \
            cp16(base_ + sOff[l], Ag + gA[l] + ko_); \
            cp16(base_ + 16384u + sOff[l], Bg + gA[l] + ko_); \
        } \
        CP_COMMIT(); \
    } while (0)

    G_ISSUE(0, 0);
    G_ISSUE(1, 1);

    const int r    = lane >> 2;
    const int c2   = (lane & 3) << 1;
    const int xor2 = (r & 3) << 1;
    const int bq   = c2 >> 2;
    const int w    = c2 & 3;
    const int arow = wm * 64 + r;
    const int brow = wn * 32 + r;

    for (int kt = 0; kt < 32; kt++) {
        if (kt + 1 < 32) { CP_WAIT(1); } else { CP_WAIT(0); }
        __syncthreads();
        if (kt + 2 < 32) G_ISSUE(kt + 2, (kt + 2) % 3);

        const uint32_t* sA = (const uint32_t*)(sm + (kt % 3) * 32768);
        const uint32_t* sB = sA + 4096;

#pragma unroll
        for (int t = 0; t < 4; t++) {
            const int coff = (((2 * t + bq) ^ xor2) << 2) + w;
            uint32_t af[4][4];
#pragma unroll
            for (int mt = 0; mt < 4; mt++) {
                const int rlo = arow + mt * 16;
                uint2 flo = *(const uint2*)&sA[rlo * 32 + coff];
                uint2 fhi = *(const uint2*)&sA[(rlo + 8) * 32 + coff];
                af[mt][0] = flo.x; af[mt][1] = fhi.x;
                af[mt][2] = flo.y; af[mt][3] = fhi.y;
            }
            uint32_t bf[4][2];
#pragma unroll
            for (int nt = 0; nt < 4; nt++) {
                uint2 f = *(const uint2*)&sB[(brow + nt * 8) * 32 + coff];
                bf[nt][0] = f.x; bf[nt][1] = f.y;
            }
#pragma unroll
            for (int mt = 0; mt < 4; mt++)
#pragma unroll
                for (int nt = 0; nt < 4; nt++)
                    mma_tf32(acc[mt][nt][0], acc[mt][nt][1], acc[mt][nt][2], acc[mt][nt][3],
                             af[mt][0], af[mt][1], af[mt][2], af[mt][3],
                             bf[nt][0], bf[nt][1]);
        }
    }
#undef G_ISSUE
}

// ---------------------------------------------------------------------------
// Combined Q/K/V projection: grid (8, 32, 3); z = 0:Q, 1:K, 2:V. fp16 outputs.
// ---------------------------------------------------------------------------
__global__ void __launch_bounds__(256, 2) qkv_proj(
    const float* __restrict__ bq, const float* __restrict__ bk,
    const float* __restrict__ bv)
{
    extern __shared__ char smc[];
    const int z = blockIdx.z;
    const float* X    = (z == 0) ? g_Xq : (z == 1) ? g_Xk : g_Xv;
    const float* W    = g_W + (size_t)z * Ee * Ee;
    const float* bias = (z == 0) ? bq : (z == 1) ? bk : bv;

    const float* Ag = X + (size_t)blockIdx.y * 128 * Ee;
    const float* Bg = W + (size_t)blockIdx.x * 128 * Ee;

    float acc[4][4][4];
    gemm_body_ca(Ag, Bg, smc, acc);

    const int tid = threadIdx.x, wid = tid >> 5, lane = tid & 31;
    const int wm = wid >> 2, wn = wid & 3;
    const int cc2 = (lane & 3) << 1;

#pragma unroll
    for (int mt = 0; mt < 4; mt++) {
#pragma unroll
        for (int nt = 0; nt < 4; nt++) {
#pragma unroll
            for (int half = 0; half < 2; half++) {
                const int row_in = wm * 64 + mt * 16 + (lane >> 2) + half * 8;
                const int col_in = wn * 32 + nt * 8 + cc2;
                float v0 = acc[mt][nt][half * 2 + 0];
                float v1 = acc[mt][nt][half * 2 + 1];
                const int m = blockIdx.y * 128 + row_in;
                const int n = blockIdx.x * 128 + col_in;
                const int b = m >> 11, sIdx = m & (Ss - 1);
                const int h = n >> 6, d = n & 63;
                if (z != 2) {
                    __half* outp = (z == 0) ? g_Q : g_K;
                    __half2 o = __floats2half2_rn(v0 + bias[n], v1 + bias[n + 1]);
                    *(__half2*)(outp + (((size_t)(b * Hh + h) * Ss + sIdx) << 6) + d) = o;
                } else {
                    __half* base = g_Vt + ((size_t)(b * Hh + h) * Dh + d) * Ss + sIdx;
                    base[0]  = __float2half_rn(v0 + bias[n]);
                    base[Ss] = __float2half_rn(v1 + bias[n + 1]);
                }
            }
        }
    }
}

// ---------------------------------------------------------------------------
// Output projection: out = attn @ Wo^T + bo (fp32 out). grid (8, 32).
// ---------------------------------------------------------------------------
__global__ void __launch_bounds__(256, 2) gemm_o(
    const float* __restrict__ bo, float* __restrict__ out)
{
    extern __shared__ char smc[];
    const float* Ag = g_attn + (size_t)blockIdx.y * 128 * Ee;
    const float* Bg = g_W + (size_t)3 * Ee * Ee + (size_t)blockIdx.x * 128 * Ee;

    float acc[4][4][4];
    gemm_body_ca(Ag, Bg, smc, acc);

    const int tid = threadIdx.x, wid = tid >> 5, lane = tid & 31;
    const int wm = wid >> 2, wn = wid & 3;
    const int cc2 = (lane & 3) << 1;

#pragma unroll
    for (int mt = 0; mt < 4; mt++) {
#pragma unroll
        for (int nt = 0; nt < 4; nt++) {
#pragma unroll
            for (int half = 0; half < 2; half++) {
                const int row_in = wm * 64 + mt * 16 + (lane >> 2) + half * 8;
                const int col_in = wn * 32 + nt * 8 + cc2;
                const int m = blockIdx.y * 128 + row_in;
                const int n = blockIdx.x * 128 + col_in;
                float2 o = { acc[mt][nt][half * 2 + 0] + bo[n],
                             acc[mt][nt][half * 2 + 1] + bo[n + 1] };
                *(float2*)(out + (size_t)m * Ee + n) = o;
            }
        }
    }
}

// ---------------------------------------------------------------------------
// scores_mix fp16 v3: 32q x 32k x 16 heads, m16n8k16 mainloop (proven);
// mix epilogue in packed f32x2 FMAs; writes logits * log2e as fp16.
// ---------------------------------------------------------------------------
__global__ void __launch_bounds__(256, 2) scores_mix_kernel(
    const float* __restrict__ Wc, const float* __restrict__ bcp)
{
    extern __shared__ __align__(16) uint16_t sbh[];   // 3 * 4608 halves
    __shared__ unsigned long long sWc2[256];          // (w, w) packed
    __shared__ float sbcl[16];                        // bc * log2e

    const int tid = threadIdx.x, lane = tid & 31, wid = tid >> 5;
    const int b  = blockIdx.z;
    const int q0 = blockIdx.y * 32, k0 = blockIdx.x * 32;

    {
        const float w = Wc[tid];
        sWc2[tid] = pk2(w, w);
    }
    if (tid < 16) sbcl[tid] = bcp[tid] * LOG2E;

    const int row = tid >> 3, ch = tid & 7;
    const size_t hstride = (size_t)Ss * Dh;
    const __half* Qb = g_Q + ((size_t)(b * Hh) * Ss + q0) * Dh;
    const __half* Kb = g_K + ((size_t)(b * Hh) * Ss + k0) * Dh;
    const int go = row * Dh + ch * 8;
    const uint32_t s0 = smem_u32(sbh);
    const uint32_t dq = (uint32_t)(row * 144 + ch * 16);

#define SM_ISSUE(h, st) do { \
        const uint32_t sb_ = s0 + (uint32_t)(st) * 9216u; \
        cp16(sb_ + dq, Qb + (size_t)(h) * hstride + go); \
        cp16(sb_ + 4608u + dq, Kb + (size_t)(h) * hstride + go); \
        CP_COMMIT(); \
    } while (0)

    SM_ISSUE(0, 0);
    SM_ISSUE(1, 1);

    const int wm = wid >> 2, wn = wid & 3;
    const int r  = lane >> 2, c2 = (lane & 3) << 1;
    const int ar0 = (wm * 16 + r) * 72, ar1 = ar0 + 8 * 72;
    const int br  = (wn * 8 + r) * 72;

    float acc[16][4];
#pragma unroll
    for (int h = 0; h < 16; h++)
#pragma unroll
        for (int j = 0; j < 4; j++) acc[h][j] = 0.f;

#pragma unroll
    for (int h = 0; h < 16; h++) {
        if (h < 15) { CP_WAIT(1); } else { CP_WAIT(0); }
        __syncthreads();
        const uint16_t* Qs = sbh + (h % 3) * 4608;
        const uint16_t* Ks = Qs + 2304;
#pragma unroll
        for (int t = 0; t < 4; t++) {
            const int cb = t * 16 + c2;
            uint32_t a0 = *(const uint32_t*)&Qs[ar0 + cb];
            uint32_t a1 = *(const uint32_t*)&Qs[ar1 + cb];
            uint32_t a2 = *(const uint32_t*)&Qs[ar0 + cb + 8];
            uint32_t a3 = *(const uint32_t*)&Qs[ar1 + cb + 8];
            uint32_t b0 = *(const uint32_t*)&Ks[br + cb];
            uint32_t b1 = *(const uint32_t*)&Ks[br + cb + 8];
            mma_f16(acc[h][0], acc[h][1], acc[h][2], acc[h][3],
                    a0, a1, a2, a3, b0, b1);
        }
        if (h + 2 < 16) SM_ISSUE(h + 2, (h + 2) % 3);
    }
#undef SM_ISSUE

    // pack raw scores into f32x2 pairs
    unsigned long long sp01[16], sp23[16];
#pragma unroll
    for (int h = 0; h < 16; h++) {
        sp01[h] = pk2(acc[h][0], acc[h][1]);
        sp23[h] = pk2(acc[h][2], acc[h][3]);
    }

    // mix in packed FMAs: out = (s[g] + sum_h w[g,h] s[h]) * (0.125*log2e) + bc*log2e
    const float SC = 0.125f * LOG2E;
    const unsigned long long sc2 = pk2(SC, SC);

    const int qrow = q0 + wm * 16 + r;
    const int kcol = k0 + wn * 8 + c2;
#pragma unroll
    for (int g = 0; g < 16; g++) {
        unsigned long long o01 = sp01[g];
        unsigned long long o23 = sp23[g];
#pragma unroll
        for (int h = 0; h < 16; h++) {
            const unsigned long long w2 = sWc2[g * 16 + h];
            o01 = fma2(w2, sp01[h], o01);
            o23 = fma2(w2, sp23[h], o23);
        }
        const float bcl = sbcl[g];
        const unsigned long long bc2 = pk2(bcl, bcl);
        o01 = fma2(o01, sc2, bc2);
        o23 = fma2(o23, sc2, bc2);
        float f0, f1, f2, f3;
        upk2(f0, f1, o01);
        upk2(f2, f3, o23);
        __half* dst = g_P + ((size_t)((b * Hh + g) * Ss) + qrow) * Ss + kcol;
        *(__half2*)dst = __floats2half2_rn(f0, f1);
        *(__half2*)(dst + (size_t)8 * Ss) = __floats2half2_rn(f2, f3);
    }
}

// ---------------------------------------------------------------------------
// pv_softmax fp16 v4: weights = 2^(logit*log2e) via ex2.approx.f32; row sums
// computed by a 9th all-ones B-column MMA (fp32 accum, matches fp16 weights).
// 3-stage cp.async pipeline, one sync per k-tile. grid (16 qt, 32 bh).
// smem: Ph[3][5120] halves + Vh[3][2560] halves = 46080 B.
// ---------------------------------------------------------------------------
__global__ void __launch_bounds__(256, 2) pv_softmax_kernel()
{
    extern __shared__ __align__(16) uint16_t pvs[];
    uint16_t* Ph = pvs;                       // 3 stages x 5120 halves
    uint16_t* Vh = pvs + 15360;               // 3 stages x 2560 halves

    const int tid = threadIdx.x, lane = tid & 31, wid = tid >> 5;
    const int qt = blockIdx.x, bh = blockIdx.y;
    const int b = bh >> 4, h = bh & 15;

    const __half* Pg = g_P  + (size_t)bh * Ss * Ss + (size_t)qt * 128 * Ss;
    const __half* Vg = g_Vt + (size_t)bh * Dh * Ss;

    const int prow = tid >> 1;
    const int phc  = (tid & 1) * 16;
    const __half* psrc = Pg + (size_t)prow * Ss + phc;
    const uint32_t pdst0 = smem_u32(Ph + prow * 40 + phc);
    const int vd = tid >> 2, vch = (tid & 3) * 8;
    const __half* vsrc = Vg + (size_t)vd * Ss + vch;
    const uint32_t vdst0 = smem_u32(Vh + vd * 40 + vch);

    float acc[8][4];
    float accs[4];
#pragma unroll
    for (int n = 0; n < 8; n++)
#pragma unroll
        for (int j = 0; j < 4; j++) acc[n][j] = 0.f;
#pragma unroll
    for (int j = 0; j < 4; j++) accs[j] = 0.f;

    const uint32_t ONES = 0x3C003C00u;        // half2(1, 1)

#define PV_ISSUE(kt, st) do { \
        const int ko_ = (kt) * 32; \
        const uint32_t pd_ = pdst0 + (uint32_t)(st) * 10240u; \
        const uint32_t vd_ = vdst0 + (uint32_t)(st) * 5120u; \
        cp16(pd_, psrc + ko_); \
        cp16(pd_ + 16, psrc + ko_ + 8); \
        cp16(vd_, vsrc + ko_); \
        CP_COMMIT(); \
    } while (0)

    PV_ISSUE(0, 0);
    PV_ISSUE(1, 1);

    const int r  = lane >> 2, c2 = (lane & 3) << 1;
    const int row0 = 16 * wid + r;

    for (int kt = 0; kt < 64; kt++) {
        const int st = kt % 3;
        if (kt + 1 < 64) { CP_WAIT(1); } else { CP_WAIT(0); }
        __syncthreads();
        if (kt + 2 < 64) PV_ISSUE(kt + 2, (kt + 2) % 3);

        const uint16_t* Pb = Ph + st * 5120;
        const uint16_t* Vb = Vh + st * 2560;

#pragma unroll
        for (int t = 0; t < 2; t++) {
            const int cb = t * 16 + c2;
            float2 p00 = __half22float2(*(const __half2*)&Pb[row0 * 40 + cb]);
            float2 p10 = __half22float2(*(const __half2*)&Pb[(row0 + 8) * 40 + cb]);
            float2 p01 = __half22float2(*(const __half2*)&Pb[row0 * 40 + cb + 8]);
            float2 p11 = __half22float2(*(const __half2*)&Pb[(row0 + 8) * 40 + cb + 8]);
            uint32_t a0 = pack2h(ex2f(p00.x), ex2f(p00.y));
            uint32_t a1 = pack2h(ex2f(p10.x), ex2f(p10.y));
            uint32_t a2 = pack2h(ex2f(p01.x), ex2f(p01.y));
            uint32_t a3 = pack2h(ex2f(p11.x), ex2f(p11.y));
#pragma unroll
            for (int n = 0; n < 8; n++) {
                uint32_t b0 = *(const uint32_t*)&Vb[(n * 8 + r) * 40 + cb];
                uint32_t b1 = *(const uint32_t*)&Vb[(n * 8 + r) * 40 + cb + 8];
                mma_f16(acc[n][0], acc[n][1], acc[n][2], acc[n][3],
                        a0, a1, a2, a3, b0, b1);
            }
            // row-sum column (all-ones B)
            mma_f16(accs[0], accs[1], accs[2], accs[3],
                    a0, a1, a2, a3, ONES, ONES);
        }
    }
#undef PV_ISSUE

    const float inv0 = 1.0f / accs[0];
    const float inv1 = 1.0f / accs[2];

    // write tf32-rounded (consumed raw by gemm_o cp.async path)
    float* obase = g_attn + ((size_t)(b * Ss + qt * 128)) * Ee + h * Dh;
#pragma unroll
    for (int n = 0; n < 8; n++) {
        float2 lo = { __uint_as_float(f2tf32(acc[n][0] * inv0)),
                      __uint_as_float(f2tf32(acc[n][1] * inv0)) };
        float2 hi = { __uint_as_float(f2tf32(acc[n][2] * inv1)),
                      __uint_as_float(f2tf32(acc[n][3] * inv1)) };
        *(float2*)(obase + (size_t)row0 * Ee + n * 8 + c2) = lo;
        *(float2*)(obase + (size_t)(row0 + 8) * Ee + n * 8 + c2) = hi;
    }
}

// ---------------------------------------------------------------------------
extern "C" void kernel_launch(void* const* d_in, const int* in_sizes, int n_in,
                              void* d_out, int out_size)
{
    const float* query = (const float*)d_in[0];
    const float* key_  = (const float*)d_in[1];
    const float* value = (const float*)d_in[2];
    const float* Wq = (const float*)d_in[3];
    const float* bq = (const float*)d_in[4];
    const float* Wk = (const float*)d_in[5];
    const float* bk = (const float*)d_in[6];
    const float* Wv = (const float*)d_in[7];
    const float* bv = (const float*)d_in[8];
    const float* Wc = (const float*)d_in[9];
    const float* bc = (const float*)d_in[10];
    const float* Wo = (const float*)d_in[11];
    const float* bo = (const float*)d_in[12];

    const int SMEM_G  = 3 * 32768;                 // 98304
    const int SMEM_SM = 3 * 9216;                  // 27648
    const int SMEM_PV = 46080;
    cudaFuncSetAttribute(qkv_proj, cudaFuncAttributeMaxDynamicSharedMemorySize, SMEM_G);
    cudaFuncSetAttribute(gemm_o,   cudaFuncAttributeMaxDynamicSharedMemorySize, SMEM_G);
    cudaFuncSetAttribute(scores_mix_kernel, cudaFuncAttributeMaxDynamicSharedMemorySize, SMEM_SM);
    cudaFuncSetAttribute(pv_softmax_kernel, cudaFuncAttributeMaxDynamicSharedMemorySize, SMEM_PV);

    const dim3 blk(256);

    // round GEMM inputs + weights to tf32
    cvt_round_kernel<<<dim3(4096, 7), blk>>>(query, key_, value, Wq, Wk, Wv, Wo);

    // combined Q/K/V projections (fp16 outputs)
    qkv_proj<<<dim3(8, 32, 3), blk, SMEM_G>>>(bq, bk, bv);

    // fused scores + head-mix -> g_P (fp16 logits * log2e)
    scores_mix_kernel<<<dim3(64, 64, 2), blk, SMEM_SM>>>(Wc, bc);

    // fused softmax (2^x) + PV -> g_attn (tf32 bits)
    pv_softmax_kernel<<<dim3(16, 32), blk, SMEM_PV>>>();

    // output projection (fp32 out)
    gemm_o<<<dim3(8, 32), blk, SMEM_G>>>(bo, (float*)d_out);
}

// round 14
// speedup vs baseline: 1.0083x; 1.0083x over previous
#include <cuda_runtime.h>
#include <cuda_fp16.h>
#include <cstdint>

// Problem constants
#define Bb 2
#define Ss 2048
#define Ee 1024
#define Hh 16
#define Dh 64
#define Mm (Bb*Ss)    // 4096
#define BHh (Bb*Hh)   // 32

#define LOG2E 1.4426950408889634f

// Scratch (device globals: allocation-guard-safe)
__device__ float  g_Xq[(size_t)Mm * Ee];         // tf32-rounded query
__device__ float  g_Xk[(size_t)Mm * Ee];         // tf32-rounded key
__device__ float  g_Xv[(size_t)Mm * Ee];         // tf32-rounded value
__device__ float  g_W[(size_t)4 * Ee * Ee];      // tf32-rounded Wq|Wk|Wv|Wo
__device__ __half g_Q[(size_t)BHh * Ss * Dh];    // [b,h,s,d] fp16
__device__ __half g_K[(size_t)BHh * Ss * Dh];    // [b,h,s,d] fp16
__device__ __half g_Vt[(size_t)BHh * Dh * Ss];   // [b,h,d,s] fp16
__device__ __half g_P[(size_t)BHh * Ss * Ss];    // 256 MB exp2(mixed logits), fp16
__device__ float  g_attn[(size_t)Mm * Ee];       // attention out (tf32 bits)

__device__ __forceinline__ uint32_t f2tf32(float f) {
    uint32_t u;
    asm("cvt.rna.tf32.f32 %0, %1;" : "=r"(u) : "f"(f));
    return u;
}

__device__ __forceinline__ float ex2f(float x) {
    float r;
    asm("ex2.approx.f32 %0, %1;" : "=f"(r) : "f"(x));
    return r;
}

__device__ __forceinline__ void mma_tf32(float& c0, float& c1, float& c2, float& c3,
                                         uint32_t a0, uint32_t a1, uint32_t a2, uint32_t a3,
                                         uint32_t b0, uint32_t b1) {
    asm volatile(
        "mma.sync.aligned.m16n8k8.row.col.f32.tf32.tf32.f32 "
        "{%0,%1,%2,%3}, {%4,%5,%6,%7}, {%8,%9}, {%0,%1,%2,%3};\n"
        : "+f"(c0), "+f"(c1), "+f"(c2), "+f"(c3)
        : "r"(a0), "r"(a1), "r"(a2), "r"(a3), "r"(b0), "r"(b1));
}

__device__ __forceinline__ void mma_f16(float& c0, float& c1, float& c2, float& c3,
                                        uint32_t a0, uint32_t a1, uint32_t a2, uint32_t a3,
                                        uint32_t b0, uint32_t b1) {
    asm volatile(
        "mma.sync.aligned.m16n8k16.row.col.f32.f16.f16.f32 "
        "{%0,%1,%2,%3}, {%4,%5,%6,%7}, {%8,%9}, {%0,%1,%2,%3};\n"
        : "+f"(c0), "+f"(c1), "+f"(c2), "+f"(c3)
        : "r"(a0), "r"(a1), "r"(a2), "r"(a3), "r"(b0), "r"(b1));
}

__device__ __forceinline__ void cp16(uint32_t dst, const void* src) {
    asm volatile("cp.async.cg.shared.global [%0], [%1], 16;\n" :: "r"(dst), "l"(src));
}
#define CP_COMMIT() asm volatile("cp.async.commit_group;\n" ::: "memory")
#define CP_WAIT(n)  asm volatile("cp.async.wait_group %0;\n" :: "n"(n) : "memory")

__device__ __forceinline__ uint32_t smem_u32(const void* p) {
    uint32_t a;
    asm("{ .reg .u64 t; cvta.to.shared.u64 t, %1; cvt.u32.u64 %0, t; }" : "=r"(a) : "l"(p));
    return a;
}

// ---------------------------------------------------------------------------
// Round inputs + weights to tf32 (rna). grid (4096, 7), 256 thr, 4 floats/thr.
// ---------------------------------------------------------------------------
__global__ void __launch_bounds__(256) cvt_round_kernel(
    const float* __restrict__ q, const float* __restrict__ k,
    const float* __restrict__ v,
    const float* __restrict__ wq, const float* __restrict__ wk,
    const float* __restrict__ wv, const float* __restrict__ wo)
{
    const int t = blockIdx.y;
    const float* src; float* dst; int n;
    switch (t) {
        case 0: src = q;  dst = g_Xq;              n = Mm * Ee; break;
        case 1: src = k;  dst = g_Xk;              n = Mm * Ee; break;
        case 2: src = v;  dst = g_Xv;              n = Mm * Ee; break;
        case 3: src = wq; dst = g_W;               n = Ee * Ee; break;
        case 4: src = wk; dst = g_W + 1048576;     n = Ee * Ee; break;
        case 5: src = wv; dst = g_W + 2097152;     n = Ee * Ee; break;
        default:src = wo; dst = g_W + 3145728;     n = Ee * Ee; break;
    }
    const int idx = (blockIdx.x * 256 + threadIdx.x) * 4;
    if (idx < n) {
        float4 f = *(const float4*)(src + idx);
        uint4 o = { f2tf32(f.x), f2tf32(f.y), f2tf32(f.z), f2tf32(f.w) };
        *(uint4*)(dst + idx) = o;
    }
}

// ---------------------------------------------------------------------------
// cp.async GEMM mainloop (proven R10): C[128x128] = A @ B^T, tf32 bits, K=1024.
// ---------------------------------------------------------------------------
__device__ __forceinline__ void gemm_body_ca(
    const float* __restrict__ Ag, const float* __restrict__ Bg,
    char* sm, float acc[4][4][4])
{
    const int tid  = threadIdx.x;
    const int lane = tid & 31;
    const int wid  = tid >> 5;
    const int wm   = wid >> 2;
    const int wn   = wid & 3;

    const uint32_t sbase = smem_u32(sm);

    int gA[4]; uint32_t sOff[4];
#pragma unroll
    for (int l = 0; l < 4; l++) {
        const int idx = tid + 256 * l;
        const int row = idx >> 3, q = idx & 7;
        gA[l]   = row * Ee + q * 4;
        sOff[l] = (uint32_t)(row * 128 + ((q ^ ((row & 3) << 1)) << 4));
    }

#pragma unroll
    for (int i = 0; i < 4; i++)
#pragma unroll
        for (int j = 0; j < 4; j++)
#pragma unroll
            for (int r2 = 0; r2 < 4; r2++) acc[i][j][r2] = 0.f;

#define G_ISSUE(kt, st) do { \
        const uint32_t base_ = sbase + (uint32_t)(st) * 32768u; \
        const int ko_ = (kt) * 32; \
        _Pragma("unroll") \
        for (int l = 0; l < 4; l++) { \
            cp16(base_ + sOff[l], Ag + gA[l] + ko_); \
            cp16(base_ + 16384u + sOff[l], Bg + gA[l] + ko_); \
        } \
        CP_COMMIT(); \
    } while (0)

    G_ISSUE(0, 0);
    G_ISSUE(1, 1);

    const int r    = lane >> 2;
    const int c2   = (lane & 3) << 1;
    const int xor2 = (r & 3) << 1;
    const int bq   = c2 >> 2;
    const int w    = c2 & 3;
    const int arow = wm * 64 + r;
    const int brow = wn * 32 + r;

    for (int kt = 0; kt < 32; kt++) {
        if (kt + 1 < 32) { CP_WAIT(1); } else { CP_WAIT(0); }
        __syncthreads();
        if (kt + 2 < 32) G_ISSUE(kt + 2, (kt + 2) % 3);

        const uint32_t* sA = (const uint32_t*)(sm + (kt % 3) * 32768);
        const uint32_t* sB = sA + 4096;

#pragma unroll
        for (int t = 0; t < 4; t++) {
            const int coff = (((2 * t + bq) ^ xor2) << 2) + w;
            uint32_t af[4][4];
#pragma unroll
            for (int mt = 0; mt < 4; mt++) {
                const int rlo = arow + mt * 16;
                uint2 flo = *(const uint2*)&sA[rlo * 32 + coff];
                uint2 fhi = *(const uint2*)&sA[(rlo + 8) * 32 + coff];
                af[mt][0] = flo.x; af[mt][1] = fhi.x;
                af[mt][2] = flo.y; af[mt][3] = fhi.y;
            }
            uint32_t bf[4][2];
#pragma unroll
            for (int nt = 0; nt < 4; nt++) {
                uint2 f = *(const uint2*)&sB[(brow + nt * 8) * 32 + coff];
                bf[nt][0] = f.x; bf[nt][1] = f.y;
            }
#pragma unroll
            for (int mt = 0; mt < 4; mt++)
#pragma unroll
                for (int nt = 0; nt < 4; nt++)
                    mma_tf32(acc[mt][nt][0], acc[mt][nt][1], acc[mt][nt][2], acc[mt][nt][3],
                             af[mt][0], af[mt][1], af[mt][2], af[mt][3],
                             bf[nt][0], bf[nt][1]);
        }
    }
#undef G_ISSUE
}

// ---------------------------------------------------------------------------
// Combined Q/K/V projection: grid (8, 32, 3); z = 0:Q, 1:K, 2:V. fp16 outputs.
// ---------------------------------------------------------------------------
__global__ void __launch_bounds__(256, 2) qkv_proj(
    const float* __restrict__ bq, const float* __restrict__ bk,
    const float* __restrict__ bv)
{
    extern __shared__ char smc[];
    const int z = blockIdx.z;
    const float* X    = (z == 0) ? g_Xq : (z == 1) ? g_Xk : g_Xv;
    const float* W    = g_W + (size_t)z * Ee * Ee;
    const float* bias = (z == 0) ? bq : (z == 1) ? bk : bv;

    const float* Ag = X + (size_t)blockIdx.y * 128 * Ee;
    const float* Bg = W + (size_t)blockIdx.x * 128 * Ee;

    float acc[4][4][4];
    gemm_body_ca(Ag, Bg, smc, acc);

    const int tid = threadIdx.x, wid = tid >> 5, lane = tid & 31;
    const int wm = wid >> 2, wn = wid & 3;
    const int cc2 = (lane & 3) << 1;

#pragma unroll
    for (int mt = 0; mt < 4; mt++) {
#pragma unroll
        for (int nt = 0; nt < 4; nt++) {
#pragma unroll
            for (int half = 0; half < 2; half++) {
                const int row_in = wm * 64 + mt * 16 + (lane >> 2) + half * 8;
                const int col_in = wn * 32 + nt * 8 + cc2;
                float v0 = acc[mt][nt][half * 2 + 0];
                float v1 = acc[mt][nt][half * 2 + 1];
                const int m = blockIdx.y * 128 + row_in;
                const int n = blockIdx.x * 128 + col_in;
                const int b = m >> 11, sIdx = m & (Ss - 1);
                const int h = n >> 6, d = n & 63;
                if (z != 2) {
                    __half* outp = (z == 0) ? g_Q : g_K;
                    __half2 o = __floats2half2_rn(v0 + bias[n], v1 + bias[n + 1]);
                    *(__half2*)(outp + (((size_t)(b * Hh + h) * Ss + sIdx) << 6) + d) = o;
                } else {
                    __half* base = g_Vt + ((size_t)(b * Hh + h) * Dh + d) * Ss + sIdx;
                    base[0]  = __float2half_rn(v0 + bias[n]);
                    base[Ss] = __float2half_rn(v1 + bias[n + 1]);
                }
            }
        }
    }
}

// ---------------------------------------------------------------------------
// Output projection: out = attn @ Wo^T + bo (fp32 out). grid (8, 32).
// ---------------------------------------------------------------------------
__global__ void __launch_bounds__(256, 2) gemm_o(
    const float* __restrict__ bo, float* __restrict__ out)
{
    extern __shared__ char smc[];
    const float* Ag = g_attn + (size_t)blockIdx.y * 128 * Ee;
    const float* Bg = g_W + (size_t)3 * Ee * Ee + (size_t)blockIdx.x * 128 * Ee;

    float acc[4][4][4];
    gemm_body_ca(Ag, Bg, smc, acc);

    const int tid = threadIdx.x, wid = tid >> 5, lane = tid & 31;
    const int wm = wid >> 2, wn = wid & 3;
    const int cc2 = (lane & 3) << 1;

#pragma unroll
    for (int mt = 0; mt < 4; mt++) {
#pragma unroll
        for (int nt = 0; nt < 4; nt++) {
#pragma unroll
            for (int half = 0; half < 2; half++) {
                const int row_in = wm * 64 + mt * 16 + (lane >> 2) + half * 8;
                const int col_in = wn * 32 + nt * 8 + cc2;
                const int m = blockIdx.y * 128 + row_in;
                const int n = blockIdx.x * 128 + col_in;
                float2 o = { acc[mt][nt][half * 2 + 0] + bo[n],
                             acc[mt][nt][half * 2 + 1] + bo[n + 1] };
                *(float2*)(out + (size_t)m * Ee + n) = o;
            }
        }
    }
}

// ---------------------------------------------------------------------------
// scores_mix fp16 v4: 32q x 32k x 16 heads, m16n8k16 mainloop (proven R11);
// scalar-FMA mix (proven R12) with folded 0.125*log2e scale, then exp2 in
// epilogue -> writes fp16 WEIGHTS exp2(mixed*log2e) to g_P.
// ---------------------------------------------------------------------------
__global__ void __launch_bounds__(256, 2) scores_mix_kernel(
    const float* __restrict__ Wc, const float* __restrict__ bcp)
{
    extern __shared__ __align__(16) uint16_t sbh[];   // 3 * 4608 halves
    __shared__ float sWc[256];
    __shared__ float sbcl[16];                        // bc * log2e

    const int tid = threadIdx.x, lane = tid & 31, wid = tid >> 5;
    const int b  = blockIdx.z;
    const int q0 = blockIdx.y * 32, k0 = blockIdx.x * 32;

    sWc[tid] = Wc[tid];
    if (tid < 16) sbcl[tid] = bcp[tid] * LOG2E;

    const int row = tid >> 3, ch = tid & 7;
    const size_t hstride = (size_t)Ss * Dh;
    const __half* Qb = g_Q + ((size_t)(b * Hh) * Ss + q0) * Dh;
    const __half* Kb = g_K + ((size_t)(b * Hh) * Ss + k0) * Dh;
    const int go = row * Dh + ch * 8;
    const uint32_t s0 = smem_u32(sbh);
    const uint32_t dq = (uint32_t)(row * 144 + ch * 16);

#define SM_ISSUE(h, st) do { \
        const uint32_t sb_ = s0 + (uint32_t)(st) * 9216u; \
        cp16(sb_ + dq, Qb + (size_t)(h) * hstride + go); \
        cp16(sb_ + 4608u + dq, Kb + (size_t)(h) * hstride + go); \
        CP_COMMIT(); \
    } while (0)

    SM_ISSUE(0, 0);
    SM_ISSUE(1, 1);

    const int wm = wid >> 2, wn = wid & 3;
    const int r  = lane >> 2, c2 = (lane & 3) << 1;
    const int ar0 = (wm * 16 + r) * 72, ar1 = ar0 + 8 * 72;
    const int br  = (wn * 8 + r) * 72;

    float acc[16][4];
#pragma unroll
    for (int h = 0; h < 16; h++)
#pragma unroll
        for (int j = 0; j < 4; j++) acc[h][j] = 0.f;

#pragma unroll
    for (int h = 0; h < 16; h++) {
        if (h < 15) { CP_WAIT(1); } else { CP_WAIT(0); }
        __syncthreads();
        const uint16_t* Qs = sbh + (h % 3) * 4608;
        const uint16_t* Ks = Qs + 2304;
#pragma unroll
        for (int t = 0; t < 4; t++) {
            const int cb = t * 16 + c2;
            uint32_t a0 = *(const uint32_t*)&Qs[ar0 + cb];
            uint32_t a1 = *(const uint32_t*)&Qs[ar1 + cb];
            uint32_t a2 = *(const uint32_t*)&Qs[ar0 + cb + 8];
            uint32_t a3 = *(const uint32_t*)&Qs[ar1 + cb + 8];
            uint32_t b0 = *(const uint32_t*)&Ks[br + cb];
            uint32_t b1 = *(const uint32_t*)&Ks[br + cb + 8];
            mma_f16(acc[h][0], acc[h][1], acc[h][2], acc[h][3],
                    a0, a1, a2, a3, b0, b1);
        }
        if (h + 2 < 16) SM_ISSUE(h + 2, (h + 2) % 3);
    }
#undef SM_ISSUE

    // mix on raw scores: m = raw[g] + sum_h w[g,h]*raw[h]
    // weight = exp2(m * (0.125*log2e) + bc*log2e)
    const float SC = 0.125f * LOG2E;
    const int qrow = q0 + wm * 16 + r;
    const int kcol = k0 + wn * 8 + c2;
#pragma unroll
    for (int g = 0; g < 16; g++) {
        float o0 = acc[g][0];
        float o1 = acc[g][1];
        float o2 = acc[g][2];
        float o3 = acc[g][3];
#pragma unroll
        for (int h = 0; h < 16; h++) {
            const float w = sWc[g * 16 + h];
            o0 += w * acc[h][0];
            o1 += w * acc[h][1];
            o2 += w * acc[h][2];
            o3 += w * acc[h][3];
        }
        const float bcl = sbcl[g];
        const float e0 = ex2f(fmaf(o0, SC, bcl));
        const float e1 = ex2f(fmaf(o1, SC, bcl));
        const float e2 = ex2f(fmaf(o2, SC, bcl));
        const float e3 = ex2f(fmaf(o3, SC, bcl));
        __half* dst = g_P + ((size_t)((b * Hh + g) * Ss) + qrow) * Ss + kcol;
        *(__half2*)dst = __floats2half2_rn(e0, e1);
        *(__half2*)(dst + (size_t)8 * Ss) = __floats2half2_rn(e2, e3);
    }
}

// ---------------------------------------------------------------------------
// pv fp16 v5: g_P holds pre-exp'd fp16 weights -> pure MMA mainloop (raw
// LDS.32 fragments, no scalar math); row sums via all-ones B-column MMA.
// 3-stage cp.async pipeline, one sync per k-tile. grid (16 qt, 32 bh).
// smem: Ph[3][5120] halves + Vh[3][2560] halves = 46080 B.
// ---------------------------------------------------------------------------
__global__ void __launch_bounds__(256, 2) pv_softmax_kernel()
{
    extern __shared__ __align__(16) uint16_t pvs[];
    uint16_t* Ph = pvs;                       // 3 stages x 5120 halves
    uint16_t* Vh = pvs + 15360;               // 3 stages x 2560 halves

    const int tid = threadIdx.x, lane = tid & 31, wid = tid >> 5;
    const int qt = blockIdx.x, bh = blockIdx.y;
    const int b = bh >> 4, h = bh & 15;

    const __half* Pg = g_P  + (size_t)bh * Ss * Ss + (size_t)qt * 128 * Ss;
    const __half* Vg = g_Vt + (size_t)bh * Dh * Ss;

    const int prow = tid >> 1;
    const int phc  = (tid & 1) * 16;
    const __half* psrc = Pg + (size_t)prow * Ss + phc;
    const uint32_t pdst0 = smem_u32(Ph + prow * 40 + phc);
    const int vd = tid >> 2, vch = (tid & 3) * 8;
    const __half* vsrc = Vg + (size_t)vd * Ss + vch;
    const uint32_t vdst0 = smem_u32(Vh + vd * 40 + vch);

    float acc[8][4];
    float accs[4];
#pragma unroll
    for (int n = 0; n < 8; n++)
#pragma unroll
        for (int j = 0; j < 4; j++) acc[n][j] = 0.f;
#pragma unroll
    for (int j = 0; j < 4; j++) accs[j] = 0.f;

    const uint32_t ONES = 0x3C003C00u;        // half2(1, 1)

#define PV_ISSUE(kt, st) do { \
        const int ko_ = (kt) * 32; \
        const uint32_t pd_ = pdst0 + (uint32_t)(st) * 10240u; \
        const uint32_t vd_ = vdst0 + (uint32_t)(st) * 5120u; \
        cp16(pd_, psrc + ko_); \
        cp16(pd_ + 16, psrc + ko_ + 8); \
        cp16(vd_, vsrc + ko_); \
        CP_COMMIT(); \
    } while (0)

    PV_ISSUE(0, 0);
    PV_ISSUE(1, 1);

    const int r  = lane >> 2, c2 = (lane & 3) << 1;
    const int row0 = 16 * wid + r;

    for (int kt = 0; kt < 64; kt++) {
        const int st = kt % 3;
        if (kt + 1 < 64) { CP_WAIT(1); } else { CP_WAIT(0); }
        __syncthreads();
        if (kt + 2 < 64) PV_ISSUE(kt + 2, (kt + 2) % 3);

        const uint16_t* Pb = Ph + st * 5120;
        const uint16_t* Vb = Vh + st * 2560;

#pragma unroll
        for (int t = 0; t < 2; t++) {
            const int cb = t * 16 + c2;
            uint32_t a0 = *(const uint32_t*)&Pb[row0 * 40 + cb];
            uint32_t a1 = *(const uint32_t*)&Pb[(row0 + 8) * 40 + cb];
            uint32_t a2 = *(const uint32_t*)&Pb[row0 * 40 + cb + 8];
            uint32_t a3 = *(const uint32_t*)&Pb[(row0 + 8) * 40 + cb + 8];
#pragma unroll
            for (int n = 0; n < 8; n++) {
                uint32_t b0 = *(const uint32_t*)&Vb[(n * 8 + r) * 40 + cb];
                uint32_t b1 = *(const uint32_t*)&Vb[(n * 8 + r) * 40 + cb + 8];
                mma_f16(acc[n][0], acc[n][1], acc[n][2], acc[n][3],
                        a0, a1, a2, a3, b0, b1);
            }
            // row-sum column (all-ones B)
            mma_f16(accs[0], accs[1], accs[2], accs[3],
                    a0, a1, a2, a3, ONES, ONES);
        }
    }
#undef PV_ISSUE

    const float inv0 = 1.0f / accs[0];
    const float inv1 = 1.0f / accs[2];

    // write tf32-rounded (consumed raw by gemm_o cp.async path)
    float* obase = g_attn + ((size_t)(b * Ss + qt * 128)) * Ee + h * Dh;
#pragma unroll
    for (int n = 0; n < 8; n++) {
        float2 lo = { __uint_as_float(f2tf32(acc[n][0] * inv0)),
                      __uint_as_float(f2tf32(acc[n][1] * inv0)) };
        float2 hi = { __uint_as_float(f2tf32(acc[n][2] * inv1)),
                      __uint_as_float(f2tf32(acc[n][3] * inv1)) };
        *(float2*)(obase + (size_t)row0 * Ee + n * 8 + c2) = lo;
        *(float2*)(obase + (size_t)(row0 + 8) * Ee + n * 8 + c2) = hi;
    }
}

// ---------------------------------------------------------------------------
extern "C" void kernel_launch(void* const* d_in, const int* in_sizes, int n_in,
                              void* d_out, int out_size)
{
    const float* query = (const float*)d_in[0];
    const float* key_  = (const float*)d_in[1];
    const float* value = (const float*)d_in[2];
    const float* Wq = (const float*)d_in[3];
    const float* bq = (const float*)d_in[4];
    const float* Wk = (const float*)d_in[5];
    const float* bk = (const float*)d_in[6];
    const float* Wv = (const float*)d_in[7];
    const float* bv = (const float*)d_in[8];
    const float* Wc = (const float*)d_in[9];
    const float* bc = (const float*)d_in[10];
    const float* Wo = (const float*)d_in[11];
    const float* bo = (const float*)d_in[12];

    const int SMEM_G  = 3 * 32768;                 // 98304
    const int SMEM_SM = 3 * 9216;                  // 27648
    const int SMEM_PV = 46080;
    cudaFuncSetAttribute(qkv_proj, cudaFuncAttributeMaxDynamicSharedMemorySize, SMEM_G);
    cudaFuncSetAttribute(gemm_o,   cudaFuncAttributeMaxDynamicSharedMemorySize, SMEM_G);
    cudaFuncSetAttribute(scores_mix_kernel, cudaFuncAttributeMaxDynamicSharedMemorySize, SMEM_SM);
    cudaFuncSetAttribute(pv_softmax_kernel, cudaFuncAttributeMaxDynamicSharedMemorySize, SMEM_PV);

    const dim3 blk(256);

    // round GEMM inputs + weights to tf32
    cvt_round_kernel<<<dim3(4096, 7), blk>>>(query, key_, value, Wq, Wk, Wv, Wo);

    // combined Q/K/V projections (fp16 outputs)
    qkv_proj<<<dim3(8, 32, 3), blk, SMEM_G>>>(bq, bk, bv);

    // fused scores + head-mix + exp2 -> g_P (fp16 softmax weights, unnormalized)
    scores_mix_kernel<<<dim3(64, 64, 2), blk, SMEM_SM>>>(Wc, bc);

    // PV + row-sum normalization -> g_attn (tf32 bits)
    pv_softmax_kernel<<<dim3(16, 32), blk, SMEM_PV>>>();

    // output projection (fp32 out)
    gemm_o<<<dim3(8, 32), blk, SMEM_G>>>(bo, (float*)d_out);
}

// round 15
// speedup vs baseline: 1.0650x; 1.0562x over previous
#include <cuda_runtime.h>
#include <cuda_fp16.h>
#include <cstdint>

// Problem constants
#define Bb 2
#define Ss 2048
#define Ee 1024
#define Hh 16
#define Dh 64
#define Mm (Bb*Ss)    // 4096
#define BHh (Bb*Hh)   // 32

#define LOG2E 1.4426950408889634f

// Scratch (device globals: allocation-guard-safe)
__device__ float  g_Xq[(size_t)Mm * Ee];         // tf32-rounded query
__device__ float  g_Xk[(size_t)Mm * Ee];         // tf32-rounded key
__device__ float  g_Xv[(size_t)Mm * Ee];         // tf32-rounded value
__device__ float  g_W[(size_t)4 * Ee * Ee];      // tf32-rounded Wq|Wk|Wv|Wo
__device__ __half g_Q[(size_t)BHh * Ss * Dh];    // [b,h,s,d] fp16
__device__ __half g_K[(size_t)BHh * Ss * Dh];    // [b,h,s,d] fp16
__device__ __half g_Vt[(size_t)BHh * Dh * Ss];   // [b,h,d,s] fp16
__device__ __half g_P[(size_t)BHh * Ss * Ss];    // 256 MB mixed logits * log2e, fp16
__device__ float  g_attn[(size_t)Mm * Ee];       // attention out (tf32 bits)

__device__ __forceinline__ uint32_t f2tf32(float f) {
    uint32_t u;
    asm("cvt.rna.tf32.f32 %0, %1;" : "=r"(u) : "f"(f));
    return u;
}

__device__ __forceinline__ uint32_t pack2h(float a, float b) {
    __half2 h = __floats2half2_rn(a, b);
    return *(uint32_t*)&h;
}

__device__ __forceinline__ float ex2f(float x) {
    float r;
    asm("ex2.approx.f32 %0, %1;" : "=f"(r) : "f"(x));
    return r;
}

__device__ __forceinline__ void mma_tf32(float& c0, float& c1, float& c2, float& c3,
                                         uint32_t a0, uint32_t a1, uint32_t a2, uint32_t a3,
                                         uint32_t b0, uint32_t b1) {
    asm volatile(
        "mma.sync.aligned.m16n8k8.row.col.f32.tf32.tf32.f32 "
        "{%0,%1,%2,%3}, {%4,%5,%6,%7}, {%8,%9}, {%0,%1,%2,%3};\n"
        : "+f"(c0), "+f"(c1), "+f"(c2), "+f"(c3)
        : "r"(a0), "r"(a1), "r"(a2), "r"(a3), "r"(b0), "r"(b1));
}

__device__ __forceinline__ void mma_f16(float& c0, float& c1, float& c2, float& c3,
                                        uint32_t a0, uint32_t a1, uint32_t a2, uint32_t a3,
                                        uint32_t b0, uint32_t b1) {
    asm volatile(
        "mma.sync.aligned.m16n8k16.row.col.f32.f16.f16.f32 "
        "{%0,%1,%2,%3}, {%4,%5,%6,%7}, {%8,%9}, {%0,%1,%2,%3};\n"
        : "+f"(c0), "+f"(c1), "+f"(c2), "+f"(c3)
        : "r"(a0), "r"(a1), "r"(a2), "r"(a3), "r"(b0), "r"(b1));
}

__device__ __forceinline__ void cp16(uint32_t dst, const void* src) {
    asm volatile("cp.async.cg.shared.global [%0], [%1], 16;\n" :: "r"(dst), "l"(src));
}
#define CP_COMMIT() asm volatile("cp.async.commit_group;\n" ::: "memory")
#define CP_WAIT(n)  asm volatile("cp.async.wait_group %0;\n" :: "n"(n) : "memory")

__device__ __forceinline__ uint32_t smem_u32(const void* p) {
    uint32_t a;
    asm("{ .reg .u64 t; cvta.to.shared.u64 t, %1; cvt.u32.u64 %0, t; }" : "=r"(a) : "l"(p));
    return a;
}

// ---------------------------------------------------------------------------
// Round inputs + weights to tf32 (rna). grid (4096, 7), 256 thr, 4 floats/thr.
// ---------------------------------------------------------------------------
__global__ void __launch_bounds__(256) cvt_round_kernel(
    const float* __restrict__ q, const float* __restrict__ k,
    const float* __restrict__ v,
    const float* __restrict__ wq, const float* __restrict__ wk,
    const float* __restrict__ wv, const float* __restrict__ wo)
{
    const int t = blockIdx.y;
    const float* src; float* dst; int n;
    switch (t) {
        case 0: src = q;  dst = g_Xq;              n = Mm * Ee; break;
        case 1: src = k;  dst = g_Xk;              n = Mm * Ee; break;
        case 2: src = v;  dst = g_Xv;              n = Mm * Ee; break;
        case 3: src = wq; dst = g_W;               n = Ee * Ee; break;
        case 4: src = wk; dst = g_W + 1048576;     n = Ee * Ee; break;
        case 5: src = wv; dst = g_W + 2097152;     n = Ee * Ee; break;
        default:src = wo; dst = g_W + 3145728;     n = Ee * Ee; break;
    }
    const int idx = (blockIdx.x * 256 + threadIdx.x) * 4;
    if (idx < n) {
        float4 f = *(const float4*)(src + idx);
        uint4 o = { f2tf32(f.x), f2tf32(f.y), f2tf32(f.z), f2tf32(f.w) };
        *(uint4*)(dst + idx) = o;
    }
}

// ---------------------------------------------------------------------------
// cp.async GEMM mainloop (proven R10): C[128x128] = A @ B^T, tf32 bits, K=1024.
// ---------------------------------------------------------------------------
__device__ __forceinline__ void gemm_body_ca(
    const float* __restrict__ Ag, const float* __restrict__ Bg,
    char* sm, float acc[4][4][4])
{
    const int tid  = threadIdx.x;
    const int lane = tid & 31;
    const int wid  = tid >> 5;
    const int wm   = wid >> 2;
    const int wn   = wid & 3;

    const uint32_t sbase = smem_u32(sm);

    int gA[4]; uint32_t sOff[4];
#pragma unroll
    for (int l = 0; l < 4; l++) {
        const int idx = tid + 256 * l;
        const int row = idx >> 3, q = idx & 7;
        gA[l]   = row * Ee + q * 4;
        sOff[l] = (uint32_t)(row * 128 + ((q ^ ((row & 3) << 1)) << 4));
    }

#pragma unroll
    for (int i = 0; i < 4; i++)
#pragma unroll
        for (int j = 0; j < 4; j++)
#pragma unroll
            for (int r2 = 0; r2 < 4; r2++) acc[i][j][r2] = 0.f;

#define G_ISSUE(kt, st) do { \
        const uint32_t base_ = sbase + (uint32_t)(st) * 32768u; \
        const int ko_ = (kt) * 32; \
        _Pragma("unroll") \
        for (int l = 0; l < 4; l++) { \
            cp16(base_ + sOff[l], Ag + gA[l] + ko_); \
            cp16(base_ + 16384u + sOff[l], Bg + gA[l] + ko_); \
        } \
        CP_COMMIT(); \
    } while (0)

    G_ISSUE(0, 0);
    G_ISSUE(1, 1);

    const int r    = lane >> 2;
    const int c2   = (lane & 3) << 1;
    const int xor2 = (r & 3) << 1;
    const int bq   = c2 >> 2;
    const int w    = c2 & 3;
    const int arow = wm * 64 + r;
    const int brow = wn * 32 + r;

    for (int kt = 0; kt < 32; kt++) {
        if (kt + 1 < 32) { CP_WAIT(1); } else { CP_WAIT(0); }
        __syncthreads();
        if (kt + 2 < 32) G_ISSUE(kt + 2, (kt + 2) % 3);

        const uint32_t* sA = (const uint32_t*)(sm + (kt % 3) * 32768);
        const uint32_t* sB = sA + 4096;

#pragma unroll
        for (int t = 0; t < 4; t++) {
            const int coff = (((2 * t + bq) ^ xor2) << 2) + w;
            uint32_t af[4][4];
#pragma unroll
            for (int mt = 0; mt < 4; mt++) {
                const int rlo = arow + mt * 16;
                uint2 flo = *(const uint2*)&sA[rlo * 32 + coff];
                uint2 fhi = *(const uint2*)&sA[(rlo + 8) * 32 + coff];
                af[mt][0] = flo.x; af[mt][1] = fhi.x;
                af[mt][2] = flo.y; af[mt][3] = fhi.y;
            }
            uint32_t bf[4][2];
#pragma unroll
            for (int nt = 0; nt < 4; nt++) {
                uint2 f = *(const uint2*)&sB[(brow + nt * 8) * 32 + coff];
                bf[nt][0] = f.x; bf[nt][1] = f.y;
            }
#pragma unroll
            for (int mt = 0; mt < 4; mt++)
#pragma unroll
                for (int nt = 0; nt < 4; nt++)
                    mma_tf32(acc[mt][nt][0], acc[mt][nt][1], acc[mt][nt][2], acc[mt][nt][3],
                             af[mt][0], af[mt][1], af[mt][2], af[mt][3],
                             bf[nt][0], bf[nt][1]);
        }
    }
#undef G_ISSUE
}

// ---------------------------------------------------------------------------
// Combined Q/K/V projection: grid (8, 32, 3); z = 0:Q, 1:K, 2:V. fp16 outputs.
// ---------------------------------------------------------------------------
__global__ void __launch_bounds__(256, 2) qkv_proj(
    const float* __restrict__ bq, const float* __restrict__ bk,
    const float* __restrict__ bv)
{
    extern __shared__ char smc[];
    const int z = blockIdx.z;
    const float* X    = (z == 0) ? g_Xq : (z == 1) ? g_Xk : g_Xv;
    const float* W    = g_W + (size_t)z * Ee * Ee;
    const float* bias = (z == 0) ? bq : (z == 1) ? bk : bv;

    const float* Ag = X + (size_t)blockIdx.y * 128 * Ee;
    const float* Bg = W + (size_t)blockIdx.x * 128 * Ee;

    float acc[4][4][4];
    gemm_body_ca(Ag, Bg, smc, acc);

    const int tid = threadIdx.x, wid = tid >> 5, lane = tid & 31;
    const int wm = wid >> 2, wn = wid & 3;
    const int cc2 = (lane & 3) << 1;

#pragma unroll
    for (int mt = 0; mt < 4; mt++) {
#pragma unroll
        for (int nt = 0; nt < 4; nt++) {
#pragma unroll
            for (int half = 0; half < 2; half++) {
                const int row_in = wm * 64 + mt * 16 + (lane >> 2) + half * 8;
                const int col_in = wn * 32 + nt * 8 + cc2;
                float v0 = acc[mt][nt][half * 2 + 0];
                float v1 = acc[mt][nt][half * 2 + 1];
                const int m = blockIdx.y * 128 + row_in;
                const int n = blockIdx.x * 128 + col_in;
                const int b = m >> 11, sIdx = m & (Ss - 1);
                const int h = n >> 6, d = n & 63;
                if (z != 2) {
                    __half* outp = (z == 0) ? g_Q : g_K;
                    __half2 o = __floats2half2_rn(v0 + bias[n], v1 + bias[n + 1]);
                    *(__half2*)(outp + (((size_t)(b * Hh + h) * Ss + sIdx) << 6) + d) = o;
                } else {
                    __half* base = g_Vt + ((size_t)(b * Hh + h) * Dh + d) * Ss + sIdx;
                    base[0]  = __float2half_rn(v0 + bias[n]);
                    base[Ss] = __float2half_rn(v1 + bias[n + 1]);
                }
            }
        }
    }
}

// ---------------------------------------------------------------------------
// Output projection: out = attn @ Wo^T + bo (fp32 out). grid (8, 32).
// ---------------------------------------------------------------------------
__global__ void __launch_bounds__(256, 2) gemm_o(
    const float* __restrict__ bo, float* __restrict__ out)
{
    extern __shared__ char smc[];
    const float* Ag = g_attn + (size_t)blockIdx.y * 128 * Ee;
    const float* Bg = g_W + (size_t)3 * Ee * Ee + (size_t)blockIdx.x * 128 * Ee;

    float acc[4][4][4];
    gemm_body_ca(Ag, Bg, smc, acc);

    const int tid = threadIdx.x, wid = tid >> 5, lane = tid & 31;
    const int wm = wid >> 2, wn = wid & 3;
    const int cc2 = (lane & 3) << 1;

#pragma unroll
    for (int mt = 0; mt < 4; mt++) {
#pragma unroll
        for (int nt = 0; nt < 4; nt++) {
#pragma unroll
            for (int half = 0; half < 2; half++) {
                const int row_in = wm * 64 + mt * 16 + (lane >> 2) + half * 8;
                const int col_in = wn * 32 + nt * 8 + cc2;
                const int m = blockIdx.y * 128 + row_in;
                const int n = blockIdx.x * 128 + col_in;
                float2 o = { acc[mt][nt][half * 2 + 0] + bo[n],
                             acc[mt][nt][half * 2 + 1] + bo[n + 1] };
                *(float2*)(out + (size_t)m * Ee + n) = o;
            }
        }
    }
}

// ---------------------------------------------------------------------------
// scores_mix fp16 v5: 32q x 32k x 16 heads; 2 HEADS PER PIPELINE STAGE
// (8 iterations, 8 MMAs/warp per sync). Scalar-FMA mix (proven R12),
// log2e folded into scale; writes fp16 logits*log2e (no exp).
// smem: 3 stages x [Q0|K0|Q1|K1] x 2304 halves = 55296 B.
// ---------------------------------------------------------------------------
__global__ void __launch_bounds__(256, 2) scores_mix_kernel(
    const float* __restrict__ Wc, const float* __restrict__ bcp)
{
    extern __shared__ __align__(16) uint16_t sbh[];   // 3 * 9216 halves
    __shared__ float sWc[256];
    __shared__ float sbcl[16];                        // bc * log2e

    const int tid = threadIdx.x, lane = tid & 31, wid = tid >> 5;
    const int b  = blockIdx.z;
    const int q0 = blockIdx.y * 32, k0 = blockIdx.x * 32;

    sWc[tid] = Wc[tid];
    if (tid < 16) sbcl[tid] = bcp[tid] * LOG2E;

    const int row = tid >> 3, ch = tid & 7;
    const size_t hstride = (size_t)Ss * Dh;
    const __half* Qb = g_Q + ((size_t)(b * Hh) * Ss + q0) * Dh;
    const __half* Kb = g_K + ((size_t)(b * Hh) * Ss + k0) * Dh;
    const int go = row * Dh + ch * 8;
    const uint32_t s0 = smem_u32(sbh);
    const uint32_t dq = (uint32_t)(row * 144 + ch * 16);

    // issue head-pair p (heads 2p, 2p+1) into stage st
#define SM_ISSUE(p, st) do { \
        const uint32_t sb_ = s0 + (uint32_t)(st) * 18432u; \
        const __half* q0_ = Qb + (size_t)(2 * (p)) * hstride; \
        const __half* k0_ = Kb + (size_t)(2 * (p)) * hstride; \
        cp16(sb_ + dq,           q0_ + go); \
        cp16(sb_ + 4608u + dq,   k0_ + go); \
        cp16(sb_ + 9216u + dq,   q0_ + hstride + go); \
        cp16(sb_ + 13824u + dq,  k0_ + hstride + go); \
        CP_COMMIT(); \
    } while (0)

    SM_ISSUE(0, 0);
    SM_ISSUE(1, 1);

    const int wm = wid >> 2, wn = wid & 3;
    const int r  = lane >> 2, c2 = (lane & 3) << 1;
    const int ar0 = (wm * 16 + r) * 72, ar1 = ar0 + 8 * 72;
    const int br  = (wn * 8 + r) * 72;

    float acc[16][4];
#pragma unroll
    for (int h = 0; h < 16; h++)
#pragma unroll
        for (int j = 0; j < 4; j++) acc[h][j] = 0.f;

#pragma unroll
    for (int p = 0; p < 8; p++) {
        if (p < 7) { CP_WAIT(1); } else { CP_WAIT(0); }
        __syncthreads();
        const uint16_t* Sg = sbh + (p % 3) * 9216;
#pragma unroll
        for (int sub = 0; sub < 2; sub++) {
            const int h = 2 * p + sub;
            const uint16_t* Qs = Sg + sub * 4608;
            const uint16_t* Ks = Qs + 2304;
#pragma unroll
            for (int t = 0; t < 4; t++) {
                const int cb = t * 16 + c2;
                uint32_t a0 = *(const uint32_t*)&Qs[ar0 + cb];
                uint32_t a1 = *(const uint32_t*)&Qs[ar1 + cb];
                uint32_t a2 = *(const uint32_t*)&Qs[ar0 + cb + 8];
                uint32_t a3 = *(const uint32_t*)&Qs[ar1 + cb + 8];
                uint32_t b0 = *(const uint32_t*)&Ks[br + cb];
                uint32_t b1 = *(const uint32_t*)&Ks[br + cb + 8];
                mma_f16(acc[h][0], acc[h][1], acc[h][2], acc[h][3],
                        a0, a1, a2, a3, b0, b1);
            }
        }
        if (p + 2 < 8) SM_ISSUE(p + 2, (p + 2) % 3);
    }
#undef SM_ISSUE

    // mix on raw scores: m = raw[g] + sum_h w[g,h]*raw[h]
    // store (m * 0.125 + bc) * log2e as fp16
    const float SC = 0.125f * LOG2E;
    const int qrow = q0 + wm * 16 + r;
    const int kcol = k0 + wn * 8 + c2;
#pragma unroll
    for (int g = 0; g < 16; g++) {
        float o0 = acc[g][0];
        float o1 = acc[g][1];
        float o2 = acc[g][2];
        float o3 = acc[g][3];
#pragma unroll
        for (int h = 0; h < 16; h++) {
            const float w = sWc[g * 16 + h];
            o0 += w * acc[h][0];
            o1 += w * acc[h][1];
            o2 += w * acc[h][2];
            o3 += w * acc[h][3];
        }
        const float bcl = sbcl[g];
        __half* dst = g_P + ((size_t)((b * Hh + g) * Ss) + qrow) * Ss + kcol;
        *(__half2*)dst = __floats2half2_rn(fmaf(o0, SC, bcl), fmaf(o1, SC, bcl));
        *(__half2*)(dst + (size_t)8 * Ss) =
            __floats2half2_rn(fmaf(o2, SC, bcl), fmaf(o3, SC, bcl));
    }
}

// ---------------------------------------------------------------------------
// pv_softmax fp16 (R13-proven): weights = 2^(logit*log2e) via ex2.approx.f32;
// row sums via all-ones B-column MMA. 3-stage cp.async, 1 sync/k-tile.
// grid (16 qt, 32 bh). smem: Ph[3][5120] + Vh[3][2560] halves = 46080 B.
// ---------------------------------------------------------------------------
__global__ void __launch_bounds__(256, 2) pv_softmax_kernel()
{
    extern __shared__ __align__(16) uint16_t pvs[];
    uint16_t* Ph = pvs;                       // 3 stages x 5120 halves
    uint16_t* Vh = pvs + 15360;               // 3 stages x 2560 halves

    const int tid = threadIdx.x, lane = tid & 31, wid = tid >> 5;
    const int qt = blockIdx.x, bh = blockIdx.y;
    const int b = bh >> 4, h = bh & 15;

    const __half* Pg = g_P  + (size_t)bh * Ss * Ss + (size_t)qt * 128 * Ss;
    const __half* Vg = g_Vt + (size_t)bh * Dh * Ss;

    const int prow = tid >> 1;
    const int phc  = (tid & 1) * 16;
    const __half* psrc = Pg + (size_t)prow * Ss + phc;
    const uint32_t pdst0 = smem_u32(Ph + prow * 40 + phc);
    const int vd = tid >> 2, vch = (tid & 3) * 8;
    const __half* vsrc = Vg + (size_t)vd * Ss + vch;
    const uint32_t vdst0 = smem_u32(Vh + vd * 40 + vch);

    float acc[8][4];
    float accs[4];
#pragma unroll
    for (int n = 0; n < 8; n++)
#pragma unroll
        for (int j = 0; j < 4; j++) acc[n][j] = 0.f;
#pragma unroll
    for (int j = 0; j < 4; j++) accs[j] = 0.f;

    const uint32_t ONES = 0x3C003C00u;        // half2(1, 1)

#define PV_ISSUE(kt, st) do { \
        const int ko_ = (kt) * 32; \
        const uint32_t pd_ = pdst0 + (uint32_t)(st) * 10240u; \
        const uint32_t vd_ = vdst0 + (uint32_t)(st) * 5120u; \
        cp16(pd_, psrc + ko_); \
        cp16(pd_ + 16, psrc + ko_ + 8); \
        cp16(vd_, vsrc + ko_); \
        CP_COMMIT(); \
    } while (0)

    PV_ISSUE(0, 0);
    PV_ISSUE(1, 1);

    const int r  = lane >> 2, c2 = (lane & 3) << 1;
    const int row0 = 16 * wid + r;

    for (int kt = 0; kt < 64; kt++) {
        const int st = kt % 3;
        if (kt + 1 < 64) { CP_WAIT(1); } else { CP_WAIT(0); }
        __syncthreads();
        if (kt + 2 < 64) PV_ISSUE(kt + 2, (kt + 2) % 3);

        const uint16_t* Pb = Ph + st * 5120;
        const uint16_t* Vb = Vh + st * 2560;

#pragma unroll
        for (int t = 0; t < 2; t++) {
            const int cb = t * 16 + c2;
            float2 p00 = __half22float2(*(const __half2*)&Pb[row0 * 40 + cb]);
            float2 p10 = __half22float2(*(const __half2*)&Pb[(row0 + 8) * 40 + cb]);
            float2 p01 = __half22float2(*(const __half2*)&Pb[row0 * 40 + cb + 8]);
            float2 p11 = __half22float2(*(const __half2*)&Pb[(row0 + 8) * 40 + cb + 8]);
            uint32_t a0 = pack2h(ex2f(p00.x), ex2f(p00.y));
            uint32_t a1 = pack2h(ex2f(p10.x), ex2f(p10.y));
            uint32_t a2 = pack2h(ex2f(p01.x), ex2f(p01.y));
            uint32_t a3 = pack2h(ex2f(p11.x), ex2f(p11.y));
#pragma unroll
            for (int n = 0; n < 8; n++) {
                uint32_t b0 = *(const uint32_t*)&Vb[(n * 8 + r) * 40 + cb];
                uint32_t b1 = *(const uint32_t*)&Vb[(n * 8 + r) * 40 + cb + 8];
                mma_f16(acc[n][0], acc[n][1], acc[n][2], acc[n][3],
                        a0, a1, a2, a3, b0, b1);
            }
            // row-sum column (all-ones B)
            mma_f16(accs[0], accs[1], accs[2], accs[3],
                    a0, a1, a2, a3, ONES, ONES);
        }
    }
#undef PV_ISSUE

    const float inv0 = 1.0f / accs[0];
    const float inv1 = 1.0f / accs[2];

    // write tf32-rounded (consumed raw by gemm_o cp.async path)
    float* obase = g_attn + ((size_t)(b * Ss + qt * 128)) * Ee + h * Dh;
#pragma unroll
    for (int n = 0; n < 8; n++) {
        float2 lo = { __uint_as_float(f2tf32(acc[n][0] * inv0)),
                      __uint_as_float(f2tf32(acc[n][1] * inv0)) };
        float2 hi = { __uint_as_float(f2tf32(acc[n][2] * inv1)),
                      __uint_as_float(f2tf32(acc[n][3] * inv1)) };
        *(float2*)(obase + (size_t)row0 * Ee + n * 8 + c2) = lo;
        *(float2*)(obase + (size_t)(row0 + 8) * Ee + n * 8 + c2) = hi;
    }
}

// ---------------------------------------------------------------------------
extern "C" void kernel_launch(void* const* d_in, const int* in_sizes, int n_in,
                              void* d_out, int out_size)
{
    const float* query = (const float*)d_in[0];
    const float* key_  = (const float*)d_in[1];
    const float* value = (const float*)d_in[2];
    const float* Wq = (const float*)d_in[3];
    const float* bq = (const float*)d_in[4];
    const float* Wk = (const float*)d_in[5];
    const float* bk = (const float*)d_in[6];
    const float* Wv = (const float*)d_in[7];
    const float* bv = (const float*)d_in[8];
    const float* Wc = (const float*)d_in[9];
    const float* bc = (const float*)d_in[10];
    const float* Wo = (const float*)d_in[11];
    const float* bo = (const float*)d_in[12];

    const int SMEM_G  = 3 * 32768;                 // 98304
    const int SMEM_SM = 3 * 18432;                 // 55296
    const int SMEM_PV = 46080;
    cudaFuncSetAttribute(qkv_proj, cudaFuncAttributeMaxDynamicSharedMemorySize, SMEM_G);
    cudaFuncSetAttribute(gemm_o,   cudaFuncAttributeMaxDynamicSharedMemorySize, SMEM_G);
    cudaFuncSetAttribute(scores_mix_kernel, cudaFuncAttributeMaxDynamicSharedMemorySize, SMEM_SM);
    cudaFuncSetAttribute(pv_softmax_kernel, cudaFuncAttributeMaxDynamicSharedMemorySize, SMEM_PV);

    const dim3 blk(256);

    // round GEMM inputs + weights to tf32
    cvt_round_kernel<<<dim3(4096, 7), blk>>>(query, key_, value, Wq, Wk, Wv, Wo);

    // combined Q/K/V projections (fp16 outputs)
    qkv_proj<<<dim3(8, 32, 3), blk, SMEM_G>>>(bq, bk, bv);

    // fused scores + head-mix -> g_P (fp16 logits * log2e)
    scores_mix_kernel<<<dim3(64, 64, 2), blk, SMEM_SM>>>(Wc, bc);

    // fused softmax (2^x) + PV -> g_attn (tf32 bits)
    pv_softmax_kernel<<<dim3(16, 32), blk, SMEM_PV>>>();

    // output projection (fp32 out)
    gemm_o<<<dim3(8, 32), blk, SMEM_G>>>(bo, (float*)d_out);
}

// round 16
// speedup vs baseline: 1.1821x; 1.1100x over previous
#include <cuda_runtime.h>
#include <cuda_fp16.h>
#include <cstdint>

// Problem constants
#define Bb 2
#define Ss 2048
#define Ee 1024
#define Hh 16
#define Dh 64
#define Mm (Bb*Ss)    // 4096
#define BHh (Bb*Hh)   // 32

#define LOG2E 1.4426950408889634f

// Scratch (device globals: allocation-guard-safe)
__device__ __half g_Xq[(size_t)Mm * Ee];         // fp16 query
__device__ __half g_Xk[(size_t)Mm * Ee];         // fp16 key
__device__ __half g_Xv[(size_t)Mm * Ee];         // fp16 value
__device__ __half g_W[(size_t)4 * Ee * Ee];      // fp16 Wq|Wk|Wv|Wo
__device__ __half g_Q[(size_t)BHh * Ss * Dh];    // [b,h,s,d] fp16
__device__ __half g_K[(size_t)BHh * Ss * Dh];    // [b,h,s,d] fp16
__device__ __half g_Vt[(size_t)BHh * Dh * Ss];   // [b,h,d,s] fp16
__device__ __half g_P[(size_t)BHh * Ss * Ss];    // 256 MB mixed logits * log2e, fp16
__device__ __half g_attn[(size_t)Mm * Ee];       // attention out, fp16

__device__ __forceinline__ uint32_t pack2h(float a, float b) {
    __half2 h = __floats2half2_rn(a, b);
    return *(uint32_t*)&h;
}

__device__ __forceinline__ float ex2f(float x) {
    float r;
    asm("ex2.approx.f32 %0, %1;" : "=f"(r) : "f"(x));
    return r;
}

__device__ __forceinline__ void mma_f16(float& c0, float& c1, float& c2, float& c3,
                                        uint32_t a0, uint32_t a1, uint32_t a2, uint32_t a3,
                                        uint32_t b0, uint32_t b1) {
    asm volatile(
        "mma.sync.aligned.m16n8k16.row.col.f32.f16.f16.f32 "
        "{%0,%1,%2,%3}, {%4,%5,%6,%7}, {%8,%9}, {%0,%1,%2,%3};\n"
        : "+f"(c0), "+f"(c1), "+f"(c2), "+f"(c3)
        : "r"(a0), "r"(a1), "r"(a2), "r"(a3), "r"(b0), "r"(b1));
}

__device__ __forceinline__ void cp16(uint32_t dst, const void* src) {
    asm volatile("cp.async.cg.shared.global [%0], [%1], 16;\n" :: "r"(dst), "l"(src));
}
#define CP_COMMIT() asm volatile("cp.async.commit_group;\n" ::: "memory")
#define CP_WAIT(n)  asm volatile("cp.async.wait_group %0;\n" :: "n"(n) : "memory")

__device__ __forceinline__ uint32_t smem_u32(const void* p) {
    uint32_t a;
    asm("{ .reg .u64 t; cvta.to.shared.u64 t, %1; cvt.u32.u64 %0, t; }" : "=r"(a) : "l"(p));
    return a;
}

// ---------------------------------------------------------------------------
// Convert inputs + weights to fp16. grid (4096, 7), 256 thr, 4 elems/thread.
// ---------------------------------------------------------------------------
__global__ void __launch_bounds__(256) cvt_kernel(
    const float* __restrict__ q, const float* __restrict__ k,
    const float* __restrict__ v,
    const float* __restrict__ wq, const float* __restrict__ wk,
    const float* __restrict__ wv, const float* __restrict__ wo)
{
    const int t = blockIdx.y;
    const float* src; __half* dst; int n;
    switch (t) {
        case 0: src = q;  dst = g_Xq;              n = Mm * Ee; break;
        case 1: src = k;  dst = g_Xk;              n = Mm * Ee; break;
        case 2: src = v;  dst = g_Xv;              n = Mm * Ee; break;
        case 3: src = wq; dst = g_W;               n = Ee * Ee; break;
        case 4: src = wk; dst = g_W + 1048576;     n = Ee * Ee; break;
        case 5: src = wv; dst = g_W + 2097152;     n = Ee * Ee; break;
        default:src = wo; dst = g_W + 3145728;     n = Ee * Ee; break;
    }
    const int idx = (blockIdx.x * 256 + threadIdx.x) * 4;
    if (idx < n) {
        float4 f = *(const float4*)(src + idx);
        uint2 o = { pack2h(f.x, f.y), pack2h(f.z, f.w) };
        *(uint2*)(dst + idx) = o;
    }
}

// ---------------------------------------------------------------------------
// fp16 cp.async GEMM mainloop: C[128x128] = A @ B^T, fp16 in / fp32 accum,
// K=1024 halves, k-tile 32. Row stride 40 halves (80 B) -> conflict-free
// LDS.32 fragments + STS, no XOR. 3-stage pipeline (stage 20480 B).
// ---------------------------------------------------------------------------
__device__ __forceinline__ void gemm_body_f16(
    const __half* __restrict__ Ag, const __half* __restrict__ Bg,
    char* sm, float acc[4][4][4])
{
    const int tid = threadIdx.x, lane = tid & 31, wid = tid >> 5;
    const int wm = wid >> 2, wn = wid & 3;
    const uint32_t sbase = smem_u32(sm);

    int gOff[2]; uint32_t sOff[2];
#pragma unroll
    for (int l = 0; l < 2; l++) {
        const int idx = tid + 256 * l;       // 0..511 chunks (16B)
        const int row = idx >> 2, q = idx & 3;
        gOff[l] = row * Ee + q * 8;          // halves
        sOff[l] = (uint32_t)(row * 80 + q * 16);
    }

#pragma unroll
    for (int i = 0; i < 4; i++)
#pragma unroll
        for (int j = 0; j < 4; j++)
#pragma unroll
            for (int r2 = 0; r2 < 4; r2++) acc[i][j][r2] = 0.f;

#define GF_ISSUE(kt, st) do { \
        const uint32_t base_ = sbase + (uint32_t)(st) * 20480u; \
        const int ko_ = (kt) * 32; \
        _Pragma("unroll") \
        for (int l = 0; l < 2; l++) { \
            cp16(base_ + sOff[l], Ag + gOff[l] + ko_); \
            cp16(base_ + 10240u + sOff[l], Bg + gOff[l] + ko_); \
        } \
        CP_COMMIT(); \
    } while (0)

    GF_ISSUE(0, 0);
    GF_ISSUE(1, 1);

    const int r = lane >> 2, c = lane & 3;
    const int arow = wm * 64 + r;
    const int brow = wn * 32 + r;

    for (int kt = 0; kt < 32; kt++) {
        if (kt + 1 < 32) { CP_WAIT(1); } else { CP_WAIT(0); }
        __syncthreads();
        if (kt + 2 < 32) GF_ISSUE(kt + 2, (kt + 2) % 3);

        const uint32_t* sA = (const uint32_t*)(sm + (kt % 3) * 20480);
        const uint32_t* sB = sA + 2560;

#pragma unroll
        for (int t = 0; t < 2; t++) {
            const int c0 = t * 8 + c;
            uint32_t af[4][4];
#pragma unroll
            for (int mt = 0; mt < 4; mt++) {
                const int base = (arow + mt * 16) * 20 + c0;
                af[mt][0] = sA[base];
                af[mt][1] = sA[base + 160];   // +8 rows
                af[mt][2] = sA[base + 4];     // +8 halves
                af[mt][3] = sA[base + 164];
            }
            uint32_t bf[4][2];
#pragma unroll
            for (int nt = 0; nt < 4; nt++) {
                const int bb = (brow + nt * 8) * 20 + c0;
                bf[nt][0] = sB[bb];
                bf[nt][1] = sB[bb + 4];
            }
#pragma unroll
            for (int mt = 0; mt < 4; mt++)
#pragma unroll
                for (int nt = 0; nt < 4; nt++)
                    mma_f16(acc[mt][nt][0], acc[mt][nt][1], acc[mt][nt][2], acc[mt][nt][3],
                            af[mt][0], af[mt][1], af[mt][2], af[mt][3],
                            bf[nt][0], bf[nt][1]);
        }
    }
#undef GF_ISSUE
}

// ---------------------------------------------------------------------------
// Combined Q/K/V projection: grid (8, 32, 3); z = 0:Q, 1:K, 2:V. fp16 outputs.
// ---------------------------------------------------------------------------
__global__ void __launch_bounds__(256, 2) qkv_proj(
    const float* __restrict__ bq, const float* __restrict__ bk,
    const float* __restrict__ bv)
{
    extern __shared__ char smc[];
    const int z = blockIdx.z;
    const __half* X    = (z == 0) ? g_Xq : (z == 1) ? g_Xk : g_Xv;
    const __half* W    = g_W + (size_t)z * Ee * Ee;
    const float* bias  = (z == 0) ? bq : (z == 1) ? bk : bv;

    const __half* Ag = X + (size_t)blockIdx.y * 128 * Ee;
    const __half* Bg = W + (size_t)blockIdx.x * 128 * Ee;

    float acc[4][4][4];
    gemm_body_f16(Ag, Bg, smc, acc);

    const int tid = threadIdx.x, wid = tid >> 5, lane = tid & 31;
    const int wm = wid >> 2, wn = wid & 3;
    const int cc2 = (lane & 3) << 1;

#pragma unroll
    for (int mt = 0; mt < 4; mt++) {
#pragma unroll
        for (int nt = 0; nt < 4; nt++) {
#pragma unroll
            for (int half = 0; half < 2; half++) {
                const int row_in = wm * 64 + mt * 16 + (lane >> 2) + half * 8;
                const int col_in = wn * 32 + nt * 8 + cc2;
                float v0 = acc[mt][nt][half * 2 + 0];
                float v1 = acc[mt][nt][half * 2 + 1];
                const int m = blockIdx.y * 128 + row_in;
                const int n = blockIdx.x * 128 + col_in;
                const int b = m >> 11, sIdx = m & (Ss - 1);
                const int h = n >> 6, d = n & 63;
                if (z != 2) {
                    __half* outp = (z == 0) ? g_Q : g_K;
                    __half2 o = __floats2half2_rn(v0 + bias[n], v1 + bias[n + 1]);
                    *(__half2*)(outp + (((size_t)(b * Hh + h) * Ss + sIdx) << 6) + d) = o;
                } else {
                    __half* base = g_Vt + ((size_t)(b * Hh + h) * Dh + d) * Ss + sIdx;
                    base[0]  = __float2half_rn(v0 + bias[n]);
                    base[Ss] = __float2half_rn(v1 + bias[n + 1]);
                }
            }
        }
    }
}

// ---------------------------------------------------------------------------
// Output projection: out = attn @ Wo^T + bo (fp32 out). grid (8, 32).
// ---------------------------------------------------------------------------
__global__ void __launch_bounds__(256, 2) gemm_o(
    const float* __restrict__ bo, float* __restrict__ out)
{
    extern __shared__ char smc[];
    const __half* Ag = g_attn + (size_t)blockIdx.y * 128 * Ee;
    const __half* Bg = g_W + (size_t)3 * Ee * Ee + (size_t)blockIdx.x * 128 * Ee;

    float acc[4][4][4];
    gemm_body_f16(Ag, Bg, smc, acc);

    const int tid = threadIdx.x, wid = tid >> 5, lane = tid & 31;
    const int wm = wid >> 2, wn = wid & 3;
    const int cc2 = (lane & 3) << 1;

#pragma unroll
    for (int mt = 0; mt < 4; mt++) {
#pragma unroll
        for (int nt = 0; nt < 4; nt++) {
#pragma unroll
            for (int half = 0; half < 2; half++) {
                const int row_in = wm * 64 + mt * 16 + (lane >> 2) + half * 8;
                const int col_in = wn * 32 + nt * 8 + cc2;
                const int m = blockIdx.y * 128 + row_in;
                const int n = blockIdx.x * 128 + col_in;
                float2 o = { acc[mt][nt][half * 2 + 0] + bo[n],
                             acc[mt][nt][half * 2 + 1] + bo[n + 1] };
                *(float2*)(out + (size_t)m * Ee + n) = o;
            }
        }
    }
}

// ---------------------------------------------------------------------------
// scores_mix fp16 v5 (proven R15): 32q x 32k x 16 heads; 2 heads per stage;
// scalar-FMA mix with log2e folded; writes fp16 logits*log2e.
// ---------------------------------------------------------------------------
__global__ void __launch_bounds__(256, 2) scores_mix_kernel(
    const float* __restrict__ Wc, const float* __restrict__ bcp)
{
    extern __shared__ __align__(16) uint16_t sbh[];   // 3 * 9216 halves
    __shared__ float sWc[256];
    __shared__ float sbcl[16];

    const int tid = threadIdx.x, lane = tid & 31, wid = tid >> 5;
    const int b  = blockIdx.z;
    const int q0 = blockIdx.y * 32, k0 = blockIdx.x * 32;

    sWc[tid] = Wc[tid];
    if (tid < 16) sbcl[tid] = bcp[tid] * LOG2E;

    const int row = tid >> 3, ch = tid & 7;
    const size_t hstride = (size_t)Ss * Dh;
    const __half* Qb = g_Q + ((size_t)(b * Hh) * Ss + q0) * Dh;
    const __half* Kb = g_K + ((size_t)(b * Hh) * Ss + k0) * Dh;
    const int go = row * Dh + ch * 8;
    const uint32_t s0 = smem_u32(sbh);
    const uint32_t dq = (uint32_t)(row * 144 + ch * 16);

#define SM_ISSUE(p, st) do { \
        const uint32_t sb_ = s0 + (uint32_t)(st) * 18432u; \
        const __half* q0_ = Qb + (size_t)(2 * (p)) * hstride; \
        const __half* k0_ = Kb + (size_t)(2 * (p)) * hstride; \
        cp16(sb_ + dq,           q0_ + go); \
        cp16(sb_ + 4608u + dq,   k0_ + go); \
        cp16(sb_ + 9216u + dq,   q0_ + hstride + go); \
        cp16(sb_ + 13824u + dq,  k0_ + hstride + go); \
        CP_COMMIT(); \
    } while (0)

    SM_ISSUE(0, 0);
    SM_ISSUE(1, 1);

    const int wm = wid >> 2, wn = wid & 3;
    const int r  = lane >> 2, c2 = (lane & 3) << 1;
    const int ar0 = (wm * 16 + r) * 72, ar1 = ar0 + 8 * 72;
    const int br  = (wn * 8 + r) * 72;

    float acc[16][4];
#pragma unroll
    for (int h = 0; h < 16; h++)
#pragma unroll
        for (int j = 0; j < 4; j++) acc[h][j] = 0.f;

#pragma unroll
    for (int p = 0; p < 8; p++) {
        if (p < 7) { CP_WAIT(1); } else { CP_WAIT(0); }
        __syncthreads();
        const uint16_t* Sg = sbh + (p % 3) * 9216;
#pragma unroll
        for (int sub = 0; sub < 2; sub++) {
            const int h = 2 * p + sub;
            const uint16_t* Qs = Sg + sub * 4608;
            const uint16_t* Ks = Qs + 2304;
#pragma unroll
            for (int t = 0; t < 4; t++) {
                const int cb = t * 16 + c2;
                uint32_t a0 = *(const uint32_t*)&Qs[ar0 + cb];
                uint32_t a1 = *(const uint32_t*)&Qs[ar1 + cb];
                uint32_t a2 = *(const uint32_t*)&Qs[ar0 + cb + 8];
                uint32_t a3 = *(const uint32_t*)&Qs[ar1 + cb + 8];
                uint32_t b0 = *(const uint32_t*)&Ks[br + cb];
                uint32_t b1 = *(const uint32_t*)&Ks[br + cb + 8];
                mma_f16(acc[h][0], acc[h][1], acc[h][2], acc[h][3],
                        a0, a1, a2, a3, b0, b1);
            }
        }
        if (p + 2 < 8) SM_ISSUE(p + 2, (p + 2) % 3);
    }
#undef SM_ISSUE

    const float SC = 0.125f * LOG2E;
    const int qrow = q0 + wm * 16 + r;
    const int kcol = k0 + wn * 8 + c2;
#pragma unroll
    for (int g = 0; g < 16; g++) {
        float o0 = acc[g][0];
        float o1 = acc[g][1];
        float o2 = acc[g][2];
        float o3 = acc[g][3];
#pragma unroll
        for (int h = 0; h < 16; h++) {
            const float w = sWc[g * 16 + h];
            o0 += w * acc[h][0];
            o1 += w * acc[h][1];
            o2 += w * acc[h][2];
            o3 += w * acc[h][3];
        }
        const float bcl = sbcl[g];
        __half* dst = g_P + ((size_t)((b * Hh + g) * Ss) + qrow) * Ss + kcol;
        *(__half2*)dst = __floats2half2_rn(fmaf(o0, SC, bcl), fmaf(o1, SC, bcl));
        *(__half2*)(dst + (size_t)8 * Ss) =
            __floats2half2_rn(fmaf(o2, SC, bcl), fmaf(o3, SC, bcl));
    }
}

// ---------------------------------------------------------------------------
// pv_softmax (proven R13/R15): weights = 2^(logit*log2e) via ex2.approx.f32;
// row sums via all-ones B-column MMA. 3-stage cp.async, 1 sync/k-tile.
// fp16 output to g_attn. grid (16 qt, 32 bh).
// ---------------------------------------------------------------------------
__global__ void __launch_bounds__(256, 2) pv_softmax_kernel()
{
    extern __shared__ __align__(16) uint16_t pvs[];
    uint16_t* Ph = pvs;                       // 3 stages x 5120 halves
    uint16_t* Vh = pvs + 15360;               // 3 stages x 2560 halves

    const int tid = threadIdx.x, lane = tid & 31, wid = tid >> 5;
    const int qt = blockIdx.x, bh = blockIdx.y;
    const int b = bh >> 4, h = bh & 15;

    const __half* Pg = g_P  + (size_t)bh * Ss * Ss + (size_t)qt * 128 * Ss;
    const __half* Vg = g_Vt + (size_t)bh * Dh * Ss;

    const int prow = tid >> 1;
    const int phc  = (tid & 1) * 16;
    const __half* psrc = Pg + (size_t)prow * Ss + phc;
    const uint32_t pdst0 = smem_u32(Ph + prow * 40 + phc);
    const int vd = tid >> 2, vch = (tid & 3) * 8;
    const __half* vsrc = Vg + (size_t)vd * Ss + vch;
    const uint32_t vdst0 = smem_u32(Vh + vd * 40 + vch);

    float acc[8][4];
    float accs[4];
#pragma unroll
    for (int n = 0; n < 8; n++)
#pragma unroll
        for (int j = 0; j < 4; j++) acc[n][j] = 0.f;
#pragma unroll
    for (int j = 0; j < 4; j++) accs[j] = 0.f;

    const uint32_t ONES = 0x3C003C00u;

#define PV_ISSUE(kt, st) do { \
        const int ko_ = (kt) * 32; \
        const uint32_t pd_ = pdst0 + (uint32_t)(st) * 10240u; \
        const uint32_t vd_ = vdst0 + (uint32_t)(st) * 5120u; \
        cp16(pd_, psrc + ko_); \
        cp16(pd_ + 16, psrc + ko_ + 8); \
        cp16(vd_, vsrc + ko_); \
        CP_COMMIT(); \
    } while (0)

    PV_ISSUE(0, 0);
    PV_ISSUE(1, 1);

    const int r  = lane >> 2, c2 = (lane & 3) << 1;
    const int row0 = 16 * wid + r;

    for (int kt = 0; kt < 64; kt++) {
        const int st = kt % 3;
        if (kt + 1 < 64) { CP_WAIT(1); } else { CP_WAIT(0); }
        __syncthreads();
        if (kt + 2 < 64) PV_ISSUE(kt + 2, (kt + 2) % 3);

        const uint16_t* Pb = Ph + st * 5120;
        const uint16_t* Vb = Vh + st * 2560;

#pragma unroll
        for (int t = 0; t < 2; t++) {
            const int cb = t * 16 + c2;
            float2 p00 = __half22float2(*(const __half2*)&Pb[row0 * 40 + cb]);
            float2 p10 = __half22float2(*(const __half2*)&Pb[(row0 + 8) * 40 + cb]);
            float2 p01 = __half22float2(*(const __half2*)&Pb[row0 * 40 + cb + 8]);
            float2 p11 = __half22float2(*(const __half2*)&Pb[(row0 + 8) * 40 + cb + 8]);
            uint32_t a0 = pack2h(ex2f(p00.x), ex2f(p00.y));
            uint32_t a1 = pack2h(ex2f(p10.x), ex2f(p10.y));
            uint32_t a2 = pack2h(ex2f(p01.x), ex2f(p01.y));
            uint32_t a3 = pack2h(ex2f(p11.x), ex2f(p11.y));
#pragma unroll
            for (int n = 0; n < 8; n++) {
                uint32_t b0 = *(const uint32_t*)&Vb[(n * 8 + r) * 40 + cb];
                uint32_t b1 = *(const uint32_t*)&Vb[(n * 8 + r) * 40 + cb + 8];
                mma_f16(acc[n][0], acc[n][1], acc[n][2], acc[n][3],
                        a0, a1, a2, a3, b0, b1);
            }
            mma_f16(accs[0], accs[1], accs[2], accs[3],
                    a0, a1, a2, a3, ONES, ONES);
        }
    }
#undef PV_ISSUE

    const float inv0 = 1.0f / accs[0];
    const float inv1 = 1.0f / accs[2];

    // write fp16 (consumed by fp16 gemm_o)
    __half* obase = g_attn + ((size_t)(b * Ss + qt * 128)) * Ee + h * Dh;
#pragma unroll
    for (int n = 0; n < 8; n++) {
        *(__half2*)(obase + (size_t)row0 * Ee + n * 8 + c2) =
            __floats2half2_rn(acc[n][0] * inv0, acc[n][1] * inv0);
        *(__half2*)(obase + (size_t)(row0 + 8) * Ee + n * 8 + c2) =
            __floats2half2_rn(acc[n][2] * inv1, acc[n][3] * inv1);
    }
}

// ---------------------------------------------------------------------------
extern "C" void kernel_launch(void* const* d_in, const int* in_sizes, int n_in,
                              void* d_out, int out_size)
{
    const float* query = (const float*)d_in[0];
    const float* key_  = (const float*)d_in[1];
    const float* value = (const float*)d_in[2];
    const float* Wq = (const float*)d_in[3];
    const float* bq = (const float*)d_in[4];
    const float* Wk = (const float*)d_in[5];
    const float* bk = (const float*)d_in[6];
    const float* Wv = (const float*)d_in[7];
    const float* bv = (const float*)d_in[8];
    const float* Wc = (const float*)d_in[9];
    const float* bc = (const float*)d_in[10];
    const float* Wo = (const float*)d_in[11];
    const float* bo = (const float*)d_in[12];

    const int SMEM_G  = 3 * 20480;                 // 61440
    const int SMEM_SM = 3 * 18432;                 // 55296
    const int SMEM_PV = 46080;
    cudaFuncSetAttribute(qkv_proj, cudaFuncAttributeMaxDynamicSharedMemorySize, SMEM_G);
    cudaFuncSetAttribute(gemm_o,   cudaFuncAttributeMaxDynamicSharedMemorySize, SMEM_G);
    cudaFuncSetAttribute(scores_mix_kernel, cudaFuncAttributeMaxDynamicSharedMemorySize, SMEM_SM);
    cudaFuncSetAttribute(pv_softmax_kernel, cudaFuncAttributeMaxDynamicSharedMemorySize, SMEM_PV);

    const dim3 blk(256);

    // convert inputs + weights to fp16
    cvt_kernel<<<dim3(4096, 7), blk>>>(query, key_, value, Wq, Wk, Wv, Wo);

    // combined Q/K/V projections (fp16 GEMM, fp16 outputs)
    qkv_proj<<<dim3(8, 32, 3), blk, SMEM_G>>>(bq, bk, bv);

    // fused scores + head-mix -> g_P (fp16 logits * log2e)
    scores_mix_kernel<<<dim3(64, 64, 2), blk, SMEM_SM>>>(Wc, bc);

    // fused softmax (2^x) + PV -> g_attn (fp16)
    pv_softmax_kernel<<<dim3(16, 32), blk, SMEM_PV>>>();

    // output projection (fp16 GEMM, fp32 out)
    gemm_o<<<dim3(8, 32), blk, SMEM_G>>>(bo, (float*)d_out);
}

// round 17
// speedup vs baseline: 1.2438x; 1.0522x over previous
#include <cuda_runtime.h>
#include <cuda_fp16.h>
#include <cstdint>

// Problem constants
#define Bb 2
#define Ss 2048
#define Ee 1024
#define Hh 16
#define Dh 64
#define Mm (Bb*Ss)    // 4096
#define BHh (Bb*Hh)   // 32

#define LOG2E 1.4426950408889634f

// Scratch (device globals: allocation-guard-safe)
__device__ __half g_Xq[(size_t)Mm * Ee];         // fp16 query
__device__ __half g_Xk[(size_t)Mm * Ee];         // fp16 key
__device__ __half g_Xv[(size_t)Mm * Ee];         // fp16 value
__device__ __half g_W[(size_t)4 * Ee * Ee];      // fp16 Wq|Wk|Wv|Wo
__device__ __half g_Q[(size_t)BHh * Ss * Dh];    // [b,h,s,d] fp16
__device__ __half g_K[(size_t)BHh * Ss * Dh];    // [b,h,s,d] fp16
__device__ __half g_Vt[(size_t)BHh * Dh * Ss];   // [b,h,d,s] fp16
__device__ __half g_P[(size_t)BHh * Ss * Ss];    // 256 MB mixed logits * log2e, fp16
__device__ __half g_attn[(size_t)Mm * Ee];       // attention out, fp16

__device__ __forceinline__ uint32_t pack2h(float a, float b) {
    __half2 h = __floats2half2_rn(a, b);
    return *(uint32_t*)&h;
}

__device__ __forceinline__ float ex2f(float x) {
    float r;
    asm("ex2.approx.f32 %0, %1;" : "=f"(r) : "f"(x));
    return r;
}

__device__ __forceinline__ void ldm_x4(uint32_t& r0, uint32_t& r1,
                                       uint32_t& r2, uint32_t& r3, uint32_t addr) {
    asm volatile("ldmatrix.sync.aligned.m8n8.x4.shared.b16 {%0,%1,%2,%3}, [%4];"
                 : "=r"(r0), "=r"(r1), "=r"(r2), "=r"(r3) : "r"(addr));
}
__device__ __forceinline__ void ldm_x2(uint32_t& r0, uint32_t& r1, uint32_t addr) {
    asm volatile("ldmatrix.sync.aligned.m8n8.x2.shared.b16 {%0,%1}, [%2];"
                 : "=r"(r0), "=r"(r1) : "r"(addr));
}

__device__ __forceinline__ void mma_f16(float& c0, float& c1, float& c2, float& c3,
                                        uint32_t a0, uint32_t a1, uint32_t a2, uint32_t a3,
                                        uint32_t b0, uint32_t b1) {
    asm volatile(
        "mma.sync.aligned.m16n8k16.row.col.f32.f16.f16.f32 "
        "{%0,%1,%2,%3}, {%4,%5,%6,%7}, {%8,%9}, {%0,%1,%2,%3};\n"
        : "+f"(c0), "+f"(c1), "+f"(c2), "+f"(c3)
        : "r"(a0), "r"(a1), "r"(a2), "r"(a3), "r"(b0), "r"(b1));
}

__device__ __forceinline__ void cp16(uint32_t dst, const void* src) {
    asm volatile("cp.async.cg.shared.global [%0], [%1], 16;\n" :: "r"(dst), "l"(src));
}
#define CP_COMMIT() asm volatile("cp.async.commit_group;\n" ::: "memory")
#define CP_WAIT(n)  asm volatile("cp.async.wait_group %0;\n" :: "n"(n) : "memory")

__device__ __forceinline__ uint32_t smem_u32(const void* p) {
    uint32_t a;
    asm("{ .reg .u64 t; cvta.to.shared.u64 t, %1; cvt.u32.u64 %0, t; }" : "=r"(a) : "l"(p));
    return a;
}

// ---------------------------------------------------------------------------
// Convert inputs + weights to fp16. grid (4096, 7), 256 thr, 4 elems/thread.
// ---------------------------------------------------------------------------
__global__ void __launch_bounds__(256) cvt_kernel(
    const float* __restrict__ q, const float* __restrict__ k,
    const float* __restrict__ v,
    const float* __restrict__ wq, const float* __restrict__ wk,
    const float* __restrict__ wv, const float* __restrict__ wo)
{
    const int t = blockIdx.y;
    const float* src; __half* dst; int n;
    switch (t) {
        case 0: src = q;  dst = g_Xq;              n = Mm * Ee; break;
        case 1: src = k;  dst = g_Xk;              n = Mm * Ee; break;
        case 2: src = v;  dst = g_Xv;              n = Mm * Ee; break;
        case 3: src = wq; dst = g_W;               n = Ee * Ee; break;
        case 4: src = wk; dst = g_W + 1048576;     n = Ee * Ee; break;
        case 5: src = wv; dst = g_W + 2097152;     n = Ee * Ee; break;
        default:src = wo; dst = g_W + 3145728;     n = Ee * Ee; break;
    }
    const int idx = (blockIdx.x * 256 + threadIdx.x) * 4;
    if (idx < n) {
        float4 f = *(const float4*)(src + idx);
        uint2 o = { pack2h(f.x, f.y), pack2h(f.z, f.w) };
        *(uint2*)(dst + idx) = o;
    }
}

// ---------------------------------------------------------------------------
// fp16 cp.async GEMM mainloop with ldmatrix fragments.
// C[128x128] = A @ B^T, fp16 in / fp32 accum, K=1024, k-tile 32.
// Row stride 40 halves (80 B). 3-stage pipeline (stage 20480 B).
// ---------------------------------------------------------------------------
__device__ __forceinline__ void gemm_body_f16(
    const __half* __restrict__ Ag, const __half* __restrict__ Bg,
    char* sm, float acc[4][4][4])
{
    const int tid = threadIdx.x, lane = tid & 31, wid = tid >> 5;
    const int wm = wid >> 2, wn = wid & 3;
    const uint32_t sbase = smem_u32(sm);

    int gOff[2]; uint32_t sOff[2];
#pragma unroll
    for (int l = 0; l < 2; l++) {
        const int idx = tid + 256 * l;       // 0..511 chunks (16B)
        const int row = idx >> 2, q = idx & 3;
        gOff[l] = row * Ee + q * 8;
        sOff[l] = (uint32_t)(row * 80 + q * 16);
    }

#pragma unroll
    for (int i = 0; i < 4; i++)
#pragma unroll
        for (int j = 0; j < 4; j++)
#pragma unroll
            for (int r2 = 0; r2 < 4; r2++) acc[i][j][r2] = 0.f;

#define GF_ISSUE(kt, st) do { \
        const uint32_t base_ = sbase + (uint32_t)(st) * 20480u; \
        const int ko_ = (kt) * 32; \
        _Pragma("unroll") \
        for (int l = 0; l < 2; l++) { \
            cp16(base_ + sOff[l], Ag + gOff[l] + ko_); \
            cp16(base_ + 10240u + sOff[l], Bg + gOff[l] + ko_); \
        } \
        CP_COMMIT(); \
    } while (0)

    GF_ISSUE(0, 0);
    GF_ISSUE(1, 1);

    // ldmatrix per-lane offsets (bytes)
    const uint32_t alo = (uint32_t)(((wm * 64 + (lane & 7) + ((lane >> 3) & 1) * 8) * 40
                                    + (lane >> 4) * 8) * 2);
    const uint32_t blo = (uint32_t)(((wn * 32 + (lane >> 4) * 8 + (lane & 7)) * 40
                                    + ((lane >> 3) & 1) * 8) * 2);

    for (int kt = 0; kt < 32; kt++) {
        if (kt + 1 < 32) { CP_WAIT(1); } else { CP_WAIT(0); }
        __syncthreads();
        if (kt + 2 < 32) GF_ISSUE(kt + 2, (kt + 2) % 3);

        const uint32_t sAb = sbase + (uint32_t)((kt % 3) * 20480);
        const uint32_t sBb = sAb + 10240u;

#pragma unroll
        for (int t = 0; t < 2; t++) {
            uint32_t af[4][4];
#pragma unroll
            for (int mt = 0; mt < 4; mt++)
                ldm_x4(af[mt][0], af[mt][1], af[mt][2], af[mt][3],
                       sAb + alo + (uint32_t)(mt * 1280 + t * 32));
            uint32_t bf[4][2];
#pragma unroll
            for (int j = 0; j < 2; j++)
                ldm_x4(bf[2 * j][0], bf[2 * j][1], bf[2 * j + 1][0], bf[2 * j + 1][1],
                       sBb + blo + (uint32_t)(j * 1280 + t * 32));
#pragma unroll
            for (int mt = 0; mt < 4; mt++)
#pragma unroll
                for (int nt = 0; nt < 4; nt++)
                    mma_f16(acc[mt][nt][0], acc[mt][nt][1], acc[mt][nt][2], acc[mt][nt][3],
                            af[mt][0], af[mt][1], af[mt][2], af[mt][3],
                            bf[nt][0], bf[nt][1]);
        }
    }
#undef GF_ISSUE
}

// ---------------------------------------------------------------------------
// Combined Q/K/V projection: grid (8, 32, 3); z = 0:Q, 1:K, 2:V. fp16 outputs.
// ---------------------------------------------------------------------------
__global__ void __launch_bounds__(256, 2) qkv_proj(
    const float* __restrict__ bq, const float* __restrict__ bk,
    const float* __restrict__ bv)
{
    extern __shared__ char smc[];
    const int z = blockIdx.z;
    const __half* X    = (z == 0) ? g_Xq : (z == 1) ? g_Xk : g_Xv;
    const __half* W    = g_W + (size_t)z * Ee * Ee;
    const float* bias  = (z == 0) ? bq : (z == 1) ? bk : bv;

    const __half* Ag = X + (size_t)blockIdx.y * 128 * Ee;
    const __half* Bg = W + (size_t)blockIdx.x * 128 * Ee;

    float acc[4][4][4];
    gemm_body_f16(Ag, Bg, smc, acc);

    const int tid = threadIdx.x, wid = tid >> 5, lane = tid & 31;
    const int wm = wid >> 2, wn = wid & 3;
    const int cc2 = (lane & 3) << 1;

#pragma unroll
    for (int mt = 0; mt < 4; mt++) {
#pragma unroll
        for (int nt = 0; nt < 4; nt++) {
#pragma unroll
            for (int half = 0; half < 2; half++) {
                const int row_in = wm * 64 + mt * 16 + (lane >> 2) + half * 8;
                const int col_in = wn * 32 + nt * 8 + cc2;
                float v0 = acc[mt][nt][half * 2 + 0];
                float v1 = acc[mt][nt][half * 2 + 1];
                const int m = blockIdx.y * 128 + row_in;
                const int n = blockIdx.x * 128 + col_in;
                const int b = m >> 11, sIdx = m & (Ss - 1);
                const int h = n >> 6, d = n & 63;
                if (z != 2) {
                    __half* outp = (z == 0) ? g_Q : g_K;
                    __half2 o = __floats2half2_rn(v0 + bias[n], v1 + bias[n + 1]);
                    *(__half2*)(outp + (((size_t)(b * Hh + h) * Ss + sIdx) << 6) + d) = o;
                } else {
                    __half* base = g_Vt + ((size_t)(b * Hh + h) * Dh + d) * Ss + sIdx;
                    base[0]  = __float2half_rn(v0 + bias[n]);
                    base[Ss] = __float2half_rn(v1 + bias[n + 1]);
                }
            }
        }
    }
}

// ---------------------------------------------------------------------------
// Output projection: out = attn @ Wo^T + bo (fp32 out). grid (8, 32).
// ---------------------------------------------------------------------------
__global__ void __launch_bounds__(256, 2) gemm_o(
    const float* __restrict__ bo, float* __restrict__ out)
{
    extern __shared__ char smc[];
    const __half* Ag = g_attn + (size_t)blockIdx.y * 128 * Ee;
    const __half* Bg = g_W + (size_t)3 * Ee * Ee + (size_t)blockIdx.x * 128 * Ee;

    float acc[4][4][4];
    gemm_body_f16(Ag, Bg, smc, acc);

    const int tid = threadIdx.x, wid = tid >> 5, lane = tid & 31;
    const int wm = wid >> 2, wn = wid & 3;
    const int cc2 = (lane & 3) << 1;

#pragma unroll
    for (int mt = 0; mt < 4; mt++) {
#pragma unroll
        for (int nt = 0; nt < 4; nt++) {
#pragma unroll
            for (int half = 0; half < 2; half++) {
                const int row_in = wm * 64 + mt * 16 + (lane >> 2) + half * 8;
                const int col_in = wn * 32 + nt * 8 + cc2;
                const int m = blockIdx.y * 128 + row_in;
                const int n = blockIdx.x * 128 + col_in;
                float2 o = { acc[mt][nt][half * 2 + 0] + bo[n],
                             acc[mt][nt][half * 2 + 1] + bo[n + 1] };
                *(float2*)(out + (size_t)m * Ee + n) = o;
            }
        }
    }
}

// ---------------------------------------------------------------------------
// scores_mix (R15 structure + ldmatrix): 32q x 32k x 16 heads; 2 heads/stage;
// scalar-FMA mix with log2e folded; writes fp16 logits*log2e.
// ---------------------------------------------------------------------------
__global__ void __launch_bounds__(256, 2) scores_mix_kernel(
    const float* __restrict__ Wc, const float* __restrict__ bcp)
{
    extern __shared__ __align__(16) uint16_t sbh[];   // 3 * 9216 halves
    __shared__ float sWc[256];
    __shared__ float sbcl[16];

    const int tid = threadIdx.x, lane = tid & 31, wid = tid >> 5;
    const int b  = blockIdx.z;
    const int q0 = blockIdx.y * 32, k0 = blockIdx.x * 32;

    sWc[tid] = Wc[tid];
    if (tid < 16) sbcl[tid] = bcp[tid] * LOG2E;

    const int row = tid >> 3, ch = tid & 7;
    const size_t hstride = (size_t)Ss * Dh;
    const __half* Qb = g_Q + ((size_t)(b * Hh) * Ss + q0) * Dh;
    const __half* Kb = g_K + ((size_t)(b * Hh) * Ss + k0) * Dh;
    const int go = row * Dh + ch * 8;
    const uint32_t s0 = smem_u32(sbh);
    const uint32_t dq = (uint32_t)(row * 144 + ch * 16);

#define SM_ISSUE(p, st) do { \
        const uint32_t sb_ = s0 + (uint32_t)(st) * 18432u; \
        const __half* q0_ = Qb + (size_t)(2 * (p)) * hstride; \
        const __half* k0_ = Kb + (size_t)(2 * (p)) * hstride; \
        cp16(sb_ + dq,           q0_ + go); \
        cp16(sb_ + 4608u + dq,   k0_ + go); \
        cp16(sb_ + 9216u + dq,   q0_ + hstride + go); \
        cp16(sb_ + 13824u + dq,  k0_ + hstride + go); \
        CP_COMMIT(); \
    } while (0)

    SM_ISSUE(0, 0);
    SM_ISSUE(1, 1);

    const int wm = wid >> 2, wn = wid & 3;
    const int r  = lane >> 2, c2 = (lane & 3) << 1;

    // ldmatrix per-lane offsets (bytes)
    const uint32_t qlo = (uint32_t)(((wm * 16 + (lane & 7) + ((lane >> 3) & 1) * 8) * 72
                                    + (lane >> 4) * 8) * 2);
    const uint32_t klo = (uint32_t)(((wn * 8 + (lane & 7)) * 72
                                    + ((lane >> 3) & 1) * 8) * 2);

    float acc[16][4];
#pragma unroll
    for (int h = 0; h < 16; h++)
#pragma unroll
        for (int j = 0; j < 4; j++) acc[h][j] = 0.f;

#pragma unroll
    for (int p = 0; p < 8; p++) {
        if (p < 7) { CP_WAIT(1); } else { CP_WAIT(0); }
        __syncthreads();
        const uint32_t Sg = s0 + (uint32_t)((p % 3) * 18432);
#pragma unroll
        for (int sub = 0; sub < 2; sub++) {
            const int h = 2 * p + sub;
            const uint32_t Qs = Sg + (uint32_t)(sub * 9216);
            const uint32_t Ks = Qs + 4608u;
#pragma unroll
            for (int t = 0; t < 4; t++) {
                uint32_t a0, a1, a2, a3, b0, b1;
                ldm_x4(a0, a1, a2, a3, Qs + qlo + (uint32_t)(t * 32));
                ldm_x2(b0, b1, Ks + klo + (uint32_t)(t * 32));
                mma_f16(acc[h][0], acc[h][1], acc[h][2], acc[h][3],
                        a0, a1, a2, a3, b0, b1);
            }
        }
        if (p + 2 < 8) SM_ISSUE(p + 2, (p + 2) % 3);
    }
#undef SM_ISSUE

    const float SC = 0.125f * LOG2E;
    const int qrow = q0 + wm * 16 + r;
    const int kcol = k0 + wn * 8 + c2;
#pragma unroll
    for (int g = 0; g < 16; g++) {
        float o0 = acc[g][0];
        float o1 = acc[g][1];
        float o2 = acc[g][2];
        float o3 = acc[g][3];
#pragma unroll
        for (int h = 0; h < 16; h++) {
            const float w = sWc[g * 16 + h];
            o0 += w * acc[h][0];
            o1 += w * acc[h][1];
            o2 += w * acc[h][2];
            o3 += w * acc[h][3];
        }
        const float bcl = sbcl[g];
        __half* dst = g_P + ((size_t)((b * Hh + g) * Ss) + qrow) * Ss + kcol;
        *(__half2*)dst = __floats2half2_rn(fmaf(o0, SC, bcl), fmaf(o1, SC, bcl));
        *(__half2*)(dst + (size_t)8 * Ss) =
            __floats2half2_rn(fmaf(o2, SC, bcl), fmaf(o3, SC, bcl));
    }
}

// ---------------------------------------------------------------------------
// pv_softmax: weights = 2^(logit*log2e) via ex2 into A-fragments; V fragments
// via ldmatrix.x4; row sums via all-ones B-column MMA. 3-stage cp.async.
// grid (16 qt, 32 bh). smem: Ph[3][5120] + Vh[3][2560] halves = 46080 B.
// ---------------------------------------------------------------------------
__global__ void __launch_bounds__(256, 2) pv_softmax_kernel()
{
    extern __shared__ __align__(16) uint16_t pvs[];
    uint16_t* Ph = pvs;                       // 3 stages x 5120 halves
    const uint32_t s0  = smem_u32(pvs);
    const uint32_t Vb0 = s0 + 30720u;         // Vh byte base

    const int tid = threadIdx.x, lane = tid & 31, wid = tid >> 5;
    const int qt = blockIdx.x, bh = blockIdx.y;
    const int b = bh >> 4, h = bh & 15;

    const __half* Pg = g_P  + (size_t)bh * Ss * Ss + (size_t)qt * 128 * Ss;
    const __half* Vg = g_Vt + (size_t)bh * Dh * Ss;

    const int prow = tid >> 1;
    const int phc  = (tid & 1) * 16;
    const __half* psrc = Pg + (size_t)prow * Ss + phc;
    const uint32_t pdst0 = s0 + (uint32_t)((prow * 40 + phc) * 2);
    const int vd = tid >> 2, vch = (tid & 3) * 8;
    const __half* vsrc = Vg + (size_t)vd * Ss + vch;
    const uint32_t vdst0 = Vb0 + (uint32_t)((vd * 40 + vch) * 2);

    // ldmatrix per-lane offset for V (bytes)
    const uint32_t vlo = (uint32_t)((((lane >> 4) * 8 + (lane & 7)) * 40
                                    + ((lane >> 3) & 1) * 8) * 2);

    float acc[8][4];
    float accs[4];
#pragma unroll
    for (int n = 0; n < 8; n++)
#pragma unroll
        for (int j = 0; j < 4; j++) acc[n][j] = 0.f;
#pragma unroll
    for (int j = 0; j < 4; j++) accs[j] = 0.f;

    const uint32_t ONES = 0x3C003C00u;

#define PV_ISSUE(kt, st) do { \
        const int ko_ = (kt) * 32; \
        const uint32_t pd_ = pdst0 + (uint32_t)(st) * 10240u; \
        const uint32_t vd_ = vdst0 + (uint32_t)(st) * 5120u; \
        cp16(pd_, psrc + ko_); \
        cp16(pd_ + 16, psrc + ko_ + 8); \
        cp16(vd_, vsrc + ko_); \
        CP_COMMIT(); \
    } while (0)

    PV_ISSUE(0, 0);
    PV_ISSUE(1, 1);

    const int r  = lane >> 2, c2 = (lane & 3) << 1;
    const int row0 = 16 * wid + r;

    for (int kt = 0; kt < 64; kt++) {
        const int st = kt % 3;
        if (kt + 1 < 64) { CP_WAIT(1); } else { CP_WAIT(0); }
        __syncthreads();
        if (kt + 2 < 64) PV_ISSUE(kt + 2, (kt + 2) % 3);

        const uint16_t* Pb = Ph + st * 5120;
        const uint32_t  Vs = Vb0 + (uint32_t)(st * 5120);

#pragma unroll
        for (int t = 0; t < 2; t++) {
            const int cb = t * 16 + c2;
            float2 p00 = __half22float2(*(const __half2*)&Pb[row0 * 40 + cb]);
            float2 p10 = __half22float2(*(const __half2*)&Pb[(row0 + 8) * 40 + cb]);
            float2 p01 = __half22float2(*(const __half2*)&Pb[row0 * 40 + cb + 8]);
            float2 p11 = __half22float2(*(const __half2*)&Pb[(row0 + 8) * 40 + cb + 8]);
            uint32_t a0 = pack2h(ex2f(p00.x), ex2f(p00.y));
            uint32_t a1 = pack2h(ex2f(p10.x), ex2f(p10.y));
            uint32_t a2 = pack2h(ex2f(p01.x), ex2f(p01.y));
            uint32_t a3 = pack2h(ex2f(p11.x), ex2f(p11.y));

            uint32_t bf[8][2];
#pragma unroll
            for (int j = 0; j < 4; j++)
                ldm_x4(bf[2 * j][0], bf[2 * j][1], bf[2 * j + 1][0], bf[2 * j + 1][1],
                       Vs + vlo + (uint32_t)(j * 1280 + t * 32));
#pragma unroll
            for (int n = 0; n < 8; n++)
                mma_f16(acc[n][0], acc[n][1], acc[n][2], acc[n][3],
                        a0, a1, a2, a3, bf[n][0], bf[n][1]);
            mma_f16(accs[0], accs[1], accs[2], accs[3],
                    a0, a1, a2, a3, ONES, ONES);
        }
    }
#undef PV_ISSUE

    const float inv0 = 1.0f / accs[0];
    const float inv1 = 1.0f / accs[2];

    __half* obase = g_attn + ((size_t)(b * Ss + qt * 128)) * Ee + h * Dh;
#pragma unroll
    for (int n = 0; n < 8; n++) {
        *(__half2*)(obase + (size_t)row0 * Ee + n * 8 + c2) =
            __floats2half2_rn(acc[n][0] * inv0, acc[n][1] * inv0);
        *(__half2*)(obase + (size_t)(row0 + 8) * Ee + n * 8 + c2) =
            __floats2half2_rn(acc[n][2] * inv1, acc[n][3] * inv1);
    }
}

// ---------------------------------------------------------------------------
extern "C" void kernel_launch(void* const* d_in, const int* in_sizes, int n_in,
                              void* d_out, int out_size)
{
    const float* query = (const float*)d_in[0];
    const float* key_  = (const float*)d_in[1];
    const float* value = (const float*)d_in[2];
    const float* Wq = (const float*)d_in[3];
    const float* bq = (const float*)d_in[4];
    const float* Wk = (const float*)d_in[5];
    const float* bk = (const float*)d_in[6];
    const float* Wv = (const float*)d_in[7];
    const float* bv = (const float*)d_in[8];
    const float* Wc = (const float*)d_in[9];
    const float* bc = (const float*)d_in[10];
    const float* Wo = (const float*)d_in[11];
    const float* bo = (const float*)d_in[12];

    const int SMEM_G  = 3 * 20480;                 // 61440
    const int SMEM_SM = 3 * 18432;                 // 55296
    const int SMEM_PV = 46080;
    cudaFuncSetAttribute(qkv_proj, cudaFuncAttributeMaxDynamicSharedMemorySize, SMEM_G);
    cudaFuncSetAttribute(gemm_o,   cudaFuncAttributeMaxDynamicSharedMemorySize, SMEM_G);
    cudaFuncSetAttribute(scores_mix_kernel, cudaFuncAttributeMaxDynamicSharedMemorySize, SMEM_SM);
    cudaFuncSetAttribute(pv_softmax_kernel, cudaFuncAttributeMaxDynamicSharedMemorySize, SMEM_PV);

    const dim3 blk(256);

    // convert inputs + weights to fp16
    cvt_kernel<<<dim3(4096, 7), blk>>>(query, key_, value, Wq, Wk, Wv, Wo);

    // combined Q/K/V projections (fp16 GEMM, fp16 outputs)
    qkv_proj<<<dim3(8, 32, 3), blk, SMEM_G>>>(bq, bk, bv);

    // fused scores + head-mix -> g_P (fp16 logits * log2e)
    scores_mix_kernel<<<dim3(64, 64, 2), blk, SMEM_SM>>>(Wc, bc);

    // fused softmax (2^x) + PV -> g_attn (fp16)
    pv_softmax_kernel<<<dim3(16, 32), blk, SMEM_PV>>>();

    // output projection (fp16 GEMM, fp32 out)
    gemm_o<<<dim3(8, 32), blk, SMEM_G>>>(bo, (float*)d_out);
}